// round 1
// baseline (speedup 1.0000x reference)
#include <cuda_runtime.h>
#include <math.h>

#define N_NODES 50000
#define F_IN    512
#define H1D     500
#define H2D     100
#define NCLS    16

// ---------------- device scratch (no allocations allowed) ----------------
__device__ __align__(16) float g_H[(size_t)N_NODES * 512];   // GEMM outputs
__device__ __align__(16) float g_A[(size_t)N_NODES * 512];   // SpMM outputs
__device__ int   g_deg[N_NODES];
__device__ float g_dinv[N_NODES];
__device__ int   g_rowptr[N_NODES + 1];
__device__ int   g_cursor[N_NODES];
__device__ int   g_colidx[800000 + N_NODES];
__device__ float g_wnorm[800000 + N_NODES];
__device__ int   g_is64;

// ---------------- graph preprocessing ----------------

// Reference asks for int64 edge_index but JAX without x64 silently yields int32.
// Detect on device: interpret first 1024 entries as int64; any value outside
// [0, N) means the data is really int32 (hi word holds the next index).
__global__ void detect_dtype_kernel(const long long* __restrict__ ei) {
    __shared__ int bad;
    if (threadIdx.x == 0) bad = 0;
    __syncthreads();
    #pragma unroll
    for (int i = 0; i < 4; ++i) {
        long long v = ei[threadIdx.x * 4 + i];
        if (v < 0 || v >= (long long)N_NODES) bad = 1;
    }
    __syncthreads();
    if (threadIdx.x == 0) g_is64 = bad ? 0 : 1;
}

__global__ void init_deg_kernel(int n) {
    int i = blockIdx.x * blockDim.x + threadIdx.x;
    if (i < n) g_deg[i] = 1;                      // self loop
}

__global__ void hist_kernel(const void* __restrict__ ei, int E) {
    int e = blockIdx.x * blockDim.x + threadIdx.x;
    if (e >= E) return;
    int r = g_is64 ? (int)((const long long*)ei)[e] : ((const int*)ei)[e];
    atomicAdd(&g_deg[r], 1);
}

__global__ void dinv_kernel(int n) {
    int i = blockIdx.x * blockDim.x + threadIdx.x;
    if (i < n) g_dinv[i] = rsqrtf((float)g_deg[i]);   // deg >= 1 always
}

// single-block exclusive scan over 50k degrees -> row_ptr (+ cursor copy)
__global__ void scan_kernel(int n) {
    __shared__ int ssum[1024];
    int t = threadIdx.x;
    int ch = (n + 1023) >> 10;
    int lo = t * ch;
    int hi = min(lo + ch, n);
    int s = 0;
    for (int i = lo; i < hi; ++i) s += g_deg[i];
    ssum[t] = s;
    __syncthreads();
    for (int off = 1; off < 1024; off <<= 1) {
        int v = (t >= off) ? ssum[t - off] : 0;
        __syncthreads();
        ssum[t] += v;
        __syncthreads();
    }
    int run = (t == 0) ? 0 : ssum[t - 1];
    for (int i = lo; i < hi; ++i) {
        g_rowptr[i] = run;
        g_cursor[i] = run;
        run += g_deg[i];
    }
    if (t == 1023) g_rowptr[n] = ssum[1023];
}

__global__ void fill_kernel(const void* __restrict__ ei, int E, int n) {
    int t = blockIdx.x * blockDim.x + threadIdx.x;
    if (t < E) {
        int r, c;
        if (g_is64) {
            r = (int)((const long long*)ei)[t];
            c = (int)((const long long*)ei)[E + t];
        } else {
            r = ((const int*)ei)[t];
            c = ((const int*)ei)[E + t];
        }
        int pos = atomicAdd(&g_cursor[r], 1);
        g_colidx[pos] = c;
        g_wnorm[pos]  = g_dinv[r] * g_dinv[c];
    } else if (t < E + n) {
        int i = t - E;
        int pos = atomicAdd(&g_cursor[i], 1);
        g_colidx[pos] = i;
        g_wnorm[pos]  = g_dinv[i] * g_dinv[i];
    }
}

// ---------------- GEMM (128x128x16, 8x8 thread tile, fully guarded) --------

__device__ __forceinline__ const float* src_buf(int id, const float* ext) {
    if (id == 0) return g_H;
    if (id == 1) return g_A;
    return ext;
}
__device__ __forceinline__ float* dst_buf(int id) { return id == 0 ? g_H : g_A; }

#define BM  128
#define BN  128
#define BKK 16
#define TM  8
#define TN  8

__global__ __launch_bounds__(256) void gemm_bias_kernel(
    const float* __restrict__ Aext, int a_id, int lda,
    const float* __restrict__ B, int ldb,
    const float* __restrict__ bias,
    int c_id, int ldc, int M, int Nn, int K)
{
    __shared__ float As[BKK][BM + 4];   // transposed A tile, +4 pad vs STS conflicts
    __shared__ float Bs[BKK][BN];
    const float* A = src_buf(a_id, Aext);
    float* C = dst_buf(c_id);

    int tid  = threadIdx.x;
    int tcol = tid & 15;
    int trow = tid >> 4;
    int m0 = blockIdx.y * BM;
    int n0 = blockIdx.x * BN;

    float acc[TM][TN];
    #pragma unroll
    for (int i = 0; i < TM; i++)
        #pragma unroll
        for (int j = 0; j < TN; j++) acc[i][j] = 0.f;

    for (int k0 = 0; k0 < K; k0 += BKK) {
        #pragma unroll
        for (int p = 0; p < (BM * BKK) / 256; ++p) {     // 8 loads / thread
            int idx = p * 256 + tid;
            int r = idx >> 4, c = idx & 15;
            float v = 0.f;
            if (m0 + r < M && k0 + c < K) v = A[(size_t)(m0 + r) * lda + k0 + c];
            As[c][r] = v;
        }
        #pragma unroll
        for (int p = 0; p < (BKK * BN) / 256; ++p) {     // 8 loads / thread
            int idx = p * 256 + tid;
            int r = idx >> 7, c = idx & 127;
            float v = 0.f;
            if (k0 + r < K && n0 + c < Nn) v = B[(size_t)(k0 + r) * ldb + n0 + c];
            Bs[r][c] = v;
        }
        __syncthreads();
        #pragma unroll
        for (int k = 0; k < BKK; ++k) {
            float a[TM], b[TN];
            #pragma unroll
            for (int i = 0; i < TM; i++) a[i] = As[k][trow * TM + i];
            #pragma unroll
            for (int j = 0; j < TN; j++) b[j] = Bs[k][tcol * TN + j];
            #pragma unroll
            for (int i = 0; i < TM; i++)
                #pragma unroll
                for (int j = 0; j < TN; j++) acc[i][j] += a[i] * b[j];
        }
        __syncthreads();
    }
    #pragma unroll
    for (int i = 0; i < TM; i++) {
        int m = m0 + trow * TM + i;
        if (m >= M) continue;
        #pragma unroll
        for (int j = 0; j < TN; j++) {
            int nn = n0 + tcol * TN + j;
            if (nn < Nn) C[(size_t)m * ldc + nn] = acc[i][j] + bias[nn];
        }
    }
}

// ---------------- SpMM (warp per row, float4 gathers) + fused tanh ----------

template<int NF4, int PITCH4, int SRC, int DST>
__global__ __launch_bounds__(256) void spmm_tanh_kernel(int n)
{
    const float4* H4 = (const float4*)(SRC == 0 ? g_H : g_A);
    float4*       O4 = (float4*)(DST == 0 ? g_H : g_A);

    int gw = (blockIdx.x * blockDim.x + threadIdx.x) >> 5;
    if (gw >= n) return;
    int lane = threadIdx.x & 31;
    constexpr int CQ = (NF4 + 31) / 32;

    float4 acc[CQ];
    #pragma unroll
    for (int q = 0; q < CQ; ++q) acc[q] = make_float4(0.f, 0.f, 0.f, 0.f);

    int s = g_rowptr[gw], e = g_rowptr[gw + 1];
    for (int j = s; j < e; ++j) {
        int   c  = g_colidx[j];           // broadcast load across warp
        float wj = g_wnorm[j];
        const float4* base = H4 + (size_t)c * PITCH4;
        #pragma unroll
        for (int q = 0; q < CQ; ++q) {
            int idx = lane + 32 * q;
            if (idx < NF4) {
                float4 v = base[idx];
                acc[q].x += wj * v.x; acc[q].y += wj * v.y;
                acc[q].z += wj * v.z; acc[q].w += wj * v.w;
            }
        }
    }
    #pragma unroll
    for (int q = 0; q < CQ; ++q) {
        int idx = lane + 32 * q;
        if (idx < NF4) {
            float4 t;
            t.x = tanhf(acc[q].x); t.y = tanhf(acc[q].y);
            t.z = tanhf(acc[q].z); t.w = tanhf(acc[q].w);
            O4[(size_t)gw * PITCH4 + idx] = t;
        }
    }
}

// ---------------- layer 3: tiny GEMM (K=100, N=16) + fused SpMM/tanh/softmax

__global__ __launch_bounds__(256) void gemm3_kernel(
    const float* __restrict__ W3, const float* __restrict__ b3, int n)
{
    __shared__ float Ws[H2D * NCLS];
    __shared__ float bs[NCLS];
    for (int i = threadIdx.x; i < H2D * NCLS; i += 256) Ws[i] = W3[i];
    if (threadIdx.x < NCLS) bs[threadIdx.x] = b3[threadIdx.x];
    __syncthreads();

    int row = blockIdx.x * blockDim.x + threadIdx.x;
    if (row >= n) return;
    float acc[NCLS];
    #pragma unroll
    for (int j = 0; j < NCLS; j++) acc[j] = bs[j];
    const float* a = g_A + (size_t)row * 128;     // pitch 128
    for (int k = 0; k < H2D; ++k) {
        float av = a[k];
        #pragma unroll
        for (int j = 0; j < NCLS; j++) acc[j] += av * Ws[k * NCLS + j];
    }
    float* o = g_H + (size_t)row * NCLS;          // pitch 16
    #pragma unroll
    for (int j = 0; j < NCLS; j++) o[j] = acc[j];
}

__global__ __launch_bounds__(256) void spmm3_softmax_kernel(float* __restrict__ out, int n)
{
    int row = blockIdx.x * blockDim.x + threadIdx.x;
    if (row >= n) return;
    float acc[NCLS];
    #pragma unroll
    for (int j = 0; j < NCLS; j++) acc[j] = 0.f;

    int s = g_rowptr[row], e = g_rowptr[row + 1];
    for (int j = s; j < e; ++j) {
        int   c  = g_colidx[j];
        float wj = g_wnorm[j];
        const float4* b = (const float4*)(g_H + (size_t)c * NCLS);
        #pragma unroll
        for (int q = 0; q < 4; ++q) {
            float4 v = b[q];
            acc[4 * q + 0] += wj * v.x; acc[4 * q + 1] += wj * v.y;
            acc[4 * q + 2] += wj * v.z; acc[4 * q + 3] += wj * v.w;
        }
    }
    float mx = -1e30f;
    #pragma unroll
    for (int j = 0; j < NCLS; j++) { acc[j] = tanhf(acc[j]); mx = fmaxf(mx, acc[j]); }
    float sum = 0.f;
    #pragma unroll
    for (int j = 0; j < NCLS; j++) { acc[j] = expf(acc[j] - mx); sum += acc[j]; }
    float inv = 1.f / sum;
    float* o = out + (size_t)row * NCLS;
    #pragma unroll
    for (int j = 0; j < NCLS; j++) o[j] = acc[j] * inv;
}

// ---------------- launch ----------------

extern "C" void kernel_launch(void* const* d_in, const int* in_sizes, int n_in,
                              void* d_out, int out_size)
{
    const float* x  = (const float*)d_in[0];
    const void*  ei = d_in[1];
    const float* W1 = (const float*)d_in[2];
    const float* b1 = (const float*)d_in[3];
    const float* W2 = (const float*)d_in[4];
    const float* b2 = (const float*)d_in[5];
    const float* W3 = (const float*)d_in[6];
    const float* b3 = (const float*)d_in[7];
    float* out = (float*)d_out;

    int n = in_sizes[0] / F_IN;   // 50000
    int E = in_sizes[1] / 2;      // 800000

    // --- CSR build (recomputed every launch; deterministic work) ---
    detect_dtype_kernel<<<1, 256>>>((const long long*)ei);
    init_deg_kernel<<<(n + 255) / 256, 256>>>(n);
    hist_kernel<<<(E + 255) / 256, 256>>>(ei, E);
    dinv_kernel<<<(n + 255) / 256, 256>>>(n);
    scan_kernel<<<1, 1024>>>(n);
    fill_kernel<<<(E + n + 255) / 256, 256>>>(ei, E, n);

    // --- layer 1: GEMM [N,512]x[512,500] -> g_H (pitch 512), SpMM+tanh -> g_A
    dim3 g1((H1D + BN - 1) / BN, (n + BM - 1) / BM);
    gemm_bias_kernel<<<g1, 256>>>(x, 2, F_IN, W1, H1D, b1, 0, 512, n, H1D, F_IN);
    spmm_tanh_kernel<125, 128, 0, 1><<<(n * 32 + 255) / 256, 256>>>(n);

    // --- layer 2: GEMM [N,500]x[500,100] -> g_H (pitch 128), SpMM+tanh -> g_A
    dim3 g2((H2D + BN - 1) / BN, (n + BM - 1) / BM);
    gemm_bias_kernel<<<g2, 256>>>(nullptr, 1, 512, W2, H2D, b2, 0, 128, n, H2D, H1D);
    spmm_tanh_kernel<25, 32, 0, 1><<<(n * 32 + 255) / 256, 256>>>(n);

    // --- layer 3: tiny GEMM -> g_H (pitch 16), fused SpMM+tanh+softmax -> out
    gemm3_kernel<<<(n + 255) / 256, 256>>>(W3, b3, n);
    spmm3_softmax_kernel<<<(n + 255) / 256, 256>>>(out, n);
}

// round 4
// speedup vs baseline: 1.6475x; 1.6475x over previous
#include <cuda_runtime.h>
#include <math.h>
#include <stdint.h>

#define N_NODES 50000
#define F_IN    512
#define H1D     500
#define H2D     100
#define NCLS    16

// ---------------- device scratch (no allocations allowed) ----------------
__device__ __align__(16) float g_H[(size_t)N_NODES * 512];   // GEMM outputs
__device__ __align__(16) float g_A[(size_t)N_NODES * 512];   // SpMM outputs
__device__ int   g_deg[N_NODES];
__device__ float g_dinv[N_NODES];
__device__ int   g_rowptr[N_NODES + 1];
__device__ int   g_cursor[N_NODES];
__device__ int   g_colidx[800000 + N_NODES];
__device__ float g_wnorm[800000 + N_NODES];
__device__ int   g_is64;

// ---------------- graph preprocessing (unchanged, passing) ---------

__global__ void detect_dtype_kernel(const long long* __restrict__ ei) {
    __shared__ int bad;
    if (threadIdx.x == 0) bad = 0;
    __syncthreads();
    #pragma unroll
    for (int i = 0; i < 4; ++i) {
        long long v = ei[threadIdx.x * 4 + i];
        if (v < 0 || v >= (long long)N_NODES) bad = 1;
    }
    __syncthreads();
    if (threadIdx.x == 0) g_is64 = bad ? 0 : 1;
}

__global__ void init_deg_kernel(int n) {
    int i = blockIdx.x * blockDim.x + threadIdx.x;
    if (i < n) g_deg[i] = 1;
}

__global__ void hist_kernel(const void* __restrict__ ei, int E) {
    int e = blockIdx.x * blockDim.x + threadIdx.x;
    if (e >= E) return;
    int r = g_is64 ? (int)((const long long*)ei)[e] : ((const int*)ei)[e];
    atomicAdd(&g_deg[r], 1);
}

__global__ void dinv_kernel(int n) {
    int i = blockIdx.x * blockDim.x + threadIdx.x;
    if (i < n) g_dinv[i] = rsqrtf((float)g_deg[i]);
}

__global__ void scan_kernel(int n) {
    __shared__ int ssum[1024];
    int t = threadIdx.x;
    int ch = (n + 1023) >> 10;
    int lo = t * ch;
    int hi = min(lo + ch, n);
    int s = 0;
    for (int i = lo; i < hi; ++i) s += g_deg[i];
    ssum[t] = s;
    __syncthreads();
    for (int off = 1; off < 1024; off <<= 1) {
        int v = (t >= off) ? ssum[t - off] : 0;
        __syncthreads();
        ssum[t] += v;
        __syncthreads();
    }
    int run = (t == 0) ? 0 : ssum[t - 1];
    for (int i = lo; i < hi; ++i) {
        g_rowptr[i] = run;
        g_cursor[i] = run;
        run += g_deg[i];
    }
    if (t == 1023) g_rowptr[n] = ssum[1023];
}

__global__ void fill_kernel(const void* __restrict__ ei, int E, int n) {
    int t = blockIdx.x * blockDim.x + threadIdx.x;
    if (t < E) {
        int r, c;
        if (g_is64) {
            r = (int)((const long long*)ei)[t];
            c = (int)((const long long*)ei)[E + t];
        } else {
            r = ((const int*)ei)[t];
            c = ((const int*)ei)[E + t];
        }
        int pos = atomicAdd(&g_cursor[r], 1);
        g_colidx[pos] = c;
        g_wnorm[pos]  = g_dinv[r] * g_dinv[c];
    } else if (t < E + n) {
        int i = t - E;
        int pos = atomicAdd(&g_cursor[i], 1);
        g_colidx[pos] = i;
        g_wnorm[pos]  = g_dinv[i] * g_dinv[i];
    }
}

// ---------------- TF32 mma.sync GEMM (sm_80+ baseline PTX, no arch gate) ----

__device__ __forceinline__ const float* src_buf(int id, const float* ext) {
    if (id == 0) return g_H;
    if (id == 1) return g_A;
    return ext;
}

__device__ __forceinline__ float ftf32(float x) {
    float y;
    asm("cvt.rna.tf32.f32 %0, %1;" : "=f"(y) : "f"(x));
    return y;
}

#define BM  128
#define BN  128
#define BK  16
#define ASTR 20     // As row stride (floats): conflict-free for frag reads
#define BSTR 136    // Bs row stride (floats): conflict-free for frag reads

// C[m][n] = sum_k A[m][k]*B[k][n] + bias[n]; C -> g_H (pitch ldc)
__global__ __launch_bounds__(256, 1) void gemm_mma_kernel(
    const float* __restrict__ Aext, int a_id, int lda,
    const float* __restrict__ B, int ldb,
    const float* __restrict__ bias,
    int ldc, int M, int Nn, int K)
{
    __shared__ float As[2][BM][ASTR];
    __shared__ float Bs[2][BK][BSTR];
    __shared__ float sbias[BN];

    const float* A = src_buf(a_id, Aext);
    float* C = g_H;

    int tid = threadIdx.x, wid = tid >> 5, lane = tid & 31;
    int g = lane >> 2, tig = lane & 3;
    int wr = wid & 3, wc = wid >> 2;            // 4x2 warp grid
    int m0 = blockIdx.y * BM, n0 = blockIdx.x * BN;

    if (tid < BN) {                              // FIX: was unguarded 256-wide write
        sbias[tid] = (n0 + tid < Nn) ? bias[n0 + tid] : 0.f;
    }

    float acc[2][8][4];
    #pragma unroll
    for (int i = 0; i < 2; i++)
        #pragma unroll
        for (int j = 0; j < 8; j++)
            #pragma unroll
            for (int q = 0; q < 4; q++) acc[i][j][q] = 0.f;

    int nIter = (K + BK - 1) >> 4;

    // ---- preload chunk 0 into buffer 0 ----
    {
        int k0 = 0;
        #pragma unroll
        for (int p = 0; p < 2; ++p) {           // A: 512 float4 / 256 thr
            int f = p * 256 + tid;
            int r = f >> 2, c4 = f & 3;
            int gm = m0 + r;
            float v[4] = {0.f, 0.f, 0.f, 0.f};
            if (gm < M) {
                if (k0 + 16 <= K) {
                    float4 t = *(const float4*)&A[(size_t)gm * lda + k0 + c4 * 4];
                    v[0] = t.x; v[1] = t.y; v[2] = t.z; v[3] = t.w;
                } else {
                    #pragma unroll
                    for (int e = 0; e < 4; ++e) {
                        int gk = k0 + c4 * 4 + e;
                        if (gk < K) v[e] = A[(size_t)gm * lda + gk];
                    }
                }
            }
            #pragma unroll
            for (int e = 0; e < 4; ++e) As[0][r][c4 * 4 + e] = ftf32(v[e]);
        }
        #pragma unroll
        for (int p = 0; p < 8; ++p) {           // B: 2048 floats / 256 thr
            int e = p * 256 + tid;
            int r = e >> 7, c = e & 127;
            int gk = k0 + r, gn = n0 + c;
            float v = (gk < K && gn < Nn) ? B[(size_t)gk * ldb + gn] : 0.f;
            Bs[0][r][c] = ftf32(v);
        }
    }
    __syncthreads();

    int buf = 0;
    for (int it = 0; it < nIter; ++it) {
        // ---- stage chunk it+1 into registers (LDG issued before MMAs) ----
        bool hasNext = (it + 1) < nIter;
        int k1 = (it + 1) << 4;
        float ra[2][4];
        float rb[8];
        if (hasNext) {
            #pragma unroll
            for (int p = 0; p < 2; ++p) {
                int f = p * 256 + tid;
                int r = f >> 2, c4 = f & 3;
                int gm = m0 + r;
                ra[p][0] = ra[p][1] = ra[p][2] = ra[p][3] = 0.f;
                if (gm < M) {
                    if (k1 + 16 <= K) {
                        float4 t = *(const float4*)&A[(size_t)gm * lda + k1 + c4 * 4];
                        ra[p][0] = t.x; ra[p][1] = t.y; ra[p][2] = t.z; ra[p][3] = t.w;
                    } else {
                        #pragma unroll
                        for (int e = 0; e < 4; ++e) {
                            int gk = k1 + c4 * 4 + e;
                            if (gk < K) ra[p][e] = A[(size_t)gm * lda + gk];
                        }
                    }
                }
            }
            #pragma unroll
            for (int p = 0; p < 8; ++p) {
                int e = p * 256 + tid;
                int r = e >> 7, c = e & 127;
                int gk = k1 + r, gn = n0 + c;
                rb[p] = (gk < K && gn < Nn) ? B[(size_t)gk * ldb + gn] : 0.f;
            }
        }

        // ---- compute on buffer buf ----
        #pragma unroll
        for (int kk = 0; kk < BK; kk += 8) {
            uint32_t af[2][4];
            #pragma unroll
            for (int i = 0; i < 2; ++i) {
                int rA = wr * 32 + i * 16;
                af[i][0] = __float_as_uint(As[buf][rA + g    ][kk + tig    ]);
                af[i][1] = __float_as_uint(As[buf][rA + g + 8][kk + tig    ]);
                af[i][2] = __float_as_uint(As[buf][rA + g    ][kk + tig + 4]);
                af[i][3] = __float_as_uint(As[buf][rA + g + 8][kk + tig + 4]);
            }
            uint32_t bf[8][2];
            #pragma unroll
            for (int j = 0; j < 8; ++j) {
                int cB = wc * 64 + j * 8 + g;
                bf[j][0] = __float_as_uint(Bs[buf][kk + tig    ][cB]);
                bf[j][1] = __float_as_uint(Bs[buf][kk + tig + 4][cB]);
            }
            #pragma unroll
            for (int i = 0; i < 2; ++i)
                #pragma unroll
                for (int j = 0; j < 8; ++j) {
                    asm volatile(
                        "mma.sync.aligned.m16n8k8.row.col.f32.tf32.tf32.f32 "
                        "{%0,%1,%2,%3}, {%4,%5,%6,%7}, {%8,%9}, {%0,%1,%2,%3};"
                        : "+f"(acc[i][j][0]), "+f"(acc[i][j][1]),
                          "+f"(acc[i][j][2]), "+f"(acc[i][j][3])
                        : "r"(af[i][0]), "r"(af[i][1]), "r"(af[i][2]), "r"(af[i][3]),
                          "r"(bf[j][0]), "r"(bf[j][1]));
                }
        }

        // ---- store staged regs into the other buffer ----
        if (hasNext) {
            int nb = buf ^ 1;
            #pragma unroll
            for (int p = 0; p < 2; ++p) {
                int f = p * 256 + tid;
                int r = f >> 2, c4 = f & 3;
                #pragma unroll
                for (int e = 0; e < 4; ++e) As[nb][r][c4 * 4 + e] = ftf32(ra[p][e]);
            }
            #pragma unroll
            for (int p = 0; p < 8; ++p) {
                int e = p * 256 + tid;
                int r = e >> 7, c = e & 127;
                Bs[nb][r][c] = ftf32(rb[p]);
            }
        }
        __syncthreads();
        buf ^= 1;
    }

    // ---- epilogue: bias add, float2 stores ----
    #pragma unroll
    for (int i = 0; i < 2; ++i) {
        int r0 = m0 + wr * 32 + i * 16 + g;
        int r1 = r0 + 8;
        #pragma unroll
        for (int j = 0; j < 8; ++j) {
            int nn = n0 + wc * 64 + j * 8 + 2 * tig;
            if (nn < Nn) {                       // Nn % 4 == 0 -> pair valid
                float b0 = sbias[wc * 64 + j * 8 + 2 * tig];
                float b1 = sbias[wc * 64 + j * 8 + 2 * tig + 1];
                if (r0 < M) {
                    float2 v = make_float2(acc[i][j][0] + b0, acc[i][j][1] + b1);
                    *(float2*)&C[(size_t)r0 * ldc + nn] = v;
                }
                if (r1 < M) {
                    float2 v = make_float2(acc[i][j][2] + b0, acc[i][j][3] + b1);
                    *(float2*)&C[(size_t)r1 * ldc + nn] = v;
                }
            }
        }
    }
}

// ---------------- SpMM (warp per row, float4 gathers) + fused tanh ----------

template<int NF4, int PITCH4, int SRC, int DST>
__global__ __launch_bounds__(256) void spmm_tanh_kernel(int n)
{
    const float4* H4 = (const float4*)(SRC == 0 ? g_H : g_A);
    float4*       O4 = (float4*)(DST == 0 ? g_H : g_A);

    int gw = (blockIdx.x * blockDim.x + threadIdx.x) >> 5;
    if (gw >= n) return;
    int lane = threadIdx.x & 31;
    constexpr int CQ = (NF4 + 31) / 32;

    float4 acc[CQ];
    #pragma unroll
    for (int q = 0; q < CQ; ++q) acc[q] = make_float4(0.f, 0.f, 0.f, 0.f);

    int s = g_rowptr[gw], e = g_rowptr[gw + 1];
    for (int j = s; j < e; ++j) {
        int   c  = g_colidx[j];
        float wj = g_wnorm[j];
        const float4* base = H4 + (size_t)c * PITCH4;
        #pragma unroll
        for (int q = 0; q < CQ; ++q) {
            int idx = lane + 32 * q;
            if (idx < NF4) {
                float4 v = base[idx];
                acc[q].x += wj * v.x; acc[q].y += wj * v.y;
                acc[q].z += wj * v.z; acc[q].w += wj * v.w;
            }
        }
    }
    #pragma unroll
    for (int q = 0; q < CQ; ++q) {
        int idx = lane + 32 * q;
        if (idx < NF4) {
            float4 t;
            t.x = tanhf(acc[q].x); t.y = tanhf(acc[q].y);
            t.z = tanhf(acc[q].z); t.w = tanhf(acc[q].w);
            O4[(size_t)gw * PITCH4 + idx] = t;
        }
    }
}

// ---------------- layer 3: tiny GEMM + fused SpMM/tanh/softmax --------------

__global__ __launch_bounds__(256) void gemm3_kernel(
    const float* __restrict__ W3, const float* __restrict__ b3, int n)
{
    __shared__ float Ws[H2D * NCLS];
    __shared__ float bs[NCLS];
    for (int i = threadIdx.x; i < H2D * NCLS; i += 256) Ws[i] = W3[i];
    if (threadIdx.x < NCLS) bs[threadIdx.x] = b3[threadIdx.x];
    __syncthreads();

    int row = blockIdx.x * blockDim.x + threadIdx.x;
    if (row >= n) return;
    float acc[NCLS];
    #pragma unroll
    for (int j = 0; j < NCLS; j++) acc[j] = bs[j];
    const float* a = g_A + (size_t)row * 128;
    for (int k = 0; k < H2D; ++k) {
        float av = a[k];
        #pragma unroll
        for (int j = 0; j < NCLS; j++) acc[j] += av * Ws[k * NCLS + j];
    }
    float* o = g_H + (size_t)row * NCLS;
    #pragma unroll
    for (int j = 0; j < NCLS; j++) o[j] = acc[j];
}

__global__ __launch_bounds__(256) void spmm3_softmax_kernel(float* __restrict__ out, int n)
{
    int row = blockIdx.x * blockDim.x + threadIdx.x;
    if (row >= n) return;
    float acc[NCLS];
    #pragma unroll
    for (int j = 0; j < NCLS; j++) acc[j] = 0.f;

    int s = g_rowptr[row], e = g_rowptr[row + 1];
    for (int j = s; j < e; ++j) {
        int   c  = g_colidx[j];
        float wj = g_wnorm[j];
        const float4* b = (const float4*)(g_H + (size_t)c * NCLS);
        #pragma unroll
        for (int q = 0; q < 4; ++q) {
            float4 v = b[q];
            acc[4 * q + 0] += wj * v.x; acc[4 * q + 1] += wj * v.y;
            acc[4 * q + 2] += wj * v.z; acc[4 * q + 3] += wj * v.w;
        }
    }
    float mx = -1e30f;
    #pragma unroll
    for (int j = 0; j < NCLS; j++) { acc[j] = tanhf(acc[j]); mx = fmaxf(mx, acc[j]); }
    float sum = 0.f;
    #pragma unroll
    for (int j = 0; j < NCLS; j++) { acc[j] = expf(acc[j] - mx); sum += acc[j]; }
    float inv = 1.f / sum;
    float* o = out + (size_t)row * NCLS;
    #pragma unroll
    for (int j = 0; j < NCLS; j++) o[j] = acc[j] * inv;
}

// ---------------- launch ----------------

extern "C" void kernel_launch(void* const* d_in, const int* in_sizes, int n_in,
                              void* d_out, int out_size)
{
    const float* x  = (const float*)d_in[0];
    const void*  ei = d_in[1];
    const float* W1 = (const float*)d_in[2];
    const float* b1 = (const float*)d_in[3];
    const float* W2 = (const float*)d_in[4];
    const float* b2 = (const float*)d_in[5];
    const float* W3 = (const float*)d_in[6];
    const float* b3 = (const float*)d_in[7];
    float* out = (float*)d_out;

    int n = in_sizes[0] / F_IN;   // 50000
    int E = in_sizes[1] / 2;      // 800000

    // --- CSR build ---
    detect_dtype_kernel<<<1, 256>>>((const long long*)ei);
    init_deg_kernel<<<(n + 255) / 256, 256>>>(n);
    hist_kernel<<<(E + 255) / 256, 256>>>(ei, E);
    dinv_kernel<<<(n + 255) / 256, 256>>>(n);
    scan_kernel<<<1, 1024>>>(n);
    fill_kernel<<<(E + n + 255) / 256, 256>>>(ei, E, n);

    // --- layer 1: TF32 GEMM [N,512]x[512,500] -> g_H (pitch 512), SpMM+tanh -> g_A
    {
        dim3 g((H1D + BN - 1) / BN, (n + BM - 1) / BM);
        gemm_mma_kernel<<<g, 256>>>(x, 2, F_IN, W1, H1D, b1, 512, n, H1D, F_IN);
    }
    spmm_tanh_kernel<125, 128, 0, 1><<<(n * 32 + 255) / 256, 256>>>(n);

    // --- layer 2: TF32 GEMM [N,500]x[500,100] -> g_H (pitch 128), SpMM+tanh -> g_A
    {
        dim3 g((H2D + BN - 1) / BN, (n + BM - 1) / BM);
        gemm_mma_kernel<<<g, 256>>>(nullptr, 1, 512, W2, H2D, b2, 128, n, H2D, H1D);
    }
    spmm_tanh_kernel<25, 32, 0, 1><<<(n * 32 + 255) / 256, 256>>>(n);

    // --- layer 3: tiny GEMM -> g_H (pitch 16), fused SpMM+tanh+softmax -> out
    gemm3_kernel<<<(n + 255) / 256, 256>>>(W3, b3, n);
    spmm3_softmax_kernel<<<(n + 255) / 256, 256>>>(out, n);
}

// round 5
// speedup vs baseline: 1.7708x; 1.0748x over previous
#include <cuda_runtime.h>
#include <cuda_fp16.h>
#include <math.h>
#include <stdint.h>

#define N_NODES 50000
#define F_IN    512
#define H1D     500
#define H2D     100
#define NCLS    16

// ---------------- device scratch (no allocations allowed) ----------------
__device__ __align__(16) float g_H[(size_t)N_NODES * 512];   // half for L1/L2 GEMM out, fp32 for gemm3
__device__ __align__(16) float g_A[(size_t)N_NODES * 512];   // SpMM outputs (fp32)
__device__ int   g_deg[N_NODES];
__device__ float g_dinv[N_NODES];
__device__ int   g_rowptr[N_NODES + 1];
__device__ int   g_cursor[N_NODES];
__device__ int   g_colidx[800000 + N_NODES];
__device__ float g_wnorm[800000 + N_NODES];
__device__ int   g_is64;

// ---------------- graph preprocessing (unchanged, passing) ---------

__global__ void detect_dtype_kernel(const long long* __restrict__ ei) {
    __shared__ int bad;
    if (threadIdx.x == 0) bad = 0;
    __syncthreads();
    #pragma unroll
    for (int i = 0; i < 4; ++i) {
        long long v = ei[threadIdx.x * 4 + i];
        if (v < 0 || v >= (long long)N_NODES) bad = 1;
    }
    __syncthreads();
    if (threadIdx.x == 0) g_is64 = bad ? 0 : 1;
}

__global__ void init_deg_kernel(int n) {
    int i = blockIdx.x * blockDim.x + threadIdx.x;
    if (i < n) g_deg[i] = 1;
}

__global__ void hist_kernel(const void* __restrict__ ei, int E) {
    int e = blockIdx.x * blockDim.x + threadIdx.x;
    if (e >= E) return;
    int r = g_is64 ? (int)((const long long*)ei)[e] : ((const int*)ei)[e];
    atomicAdd(&g_deg[r], 1);
}

__global__ void dinv_kernel(int n) {
    int i = blockIdx.x * blockDim.x + threadIdx.x;
    if (i < n) g_dinv[i] = rsqrtf((float)g_deg[i]);
}

__global__ void scan_kernel(int n) {
    __shared__ int ssum[1024];
    int t = threadIdx.x;
    int ch = (n + 1023) >> 10;
    int lo = t * ch;
    int hi = min(lo + ch, n);
    int s = 0;
    for (int i = lo; i < hi; ++i) s += g_deg[i];
    ssum[t] = s;
    __syncthreads();
    for (int off = 1; off < 1024; off <<= 1) {
        int v = (t >= off) ? ssum[t - off] : 0;
        __syncthreads();
        ssum[t] += v;
        __syncthreads();
    }
    int run = (t == 0) ? 0 : ssum[t - 1];
    for (int i = lo; i < hi; ++i) {
        g_rowptr[i] = run;
        g_cursor[i] = run;
        run += g_deg[i];
    }
    if (t == 1023) g_rowptr[n] = ssum[1023];
}

__global__ void fill_kernel(const void* __restrict__ ei, int E, int n) {
    int t = blockIdx.x * blockDim.x + threadIdx.x;
    if (t < E) {
        int r, c;
        if (g_is64) {
            r = (int)((const long long*)ei)[t];
            c = (int)((const long long*)ei)[E + t];
        } else {
            r = ((const int*)ei)[t];
            c = ((const int*)ei)[E + t];
        }
        int pos = atomicAdd(&g_cursor[r], 1);
        g_colidx[pos] = c;
        g_wnorm[pos]  = g_dinv[r] * g_dinv[c];
    } else if (t < E + n) {
        int i = t - E;
        int pos = atomicAdd(&g_cursor[i], 1);
        g_colidx[pos] = i;
        g_wnorm[pos]  = g_dinv[i] * g_dinv[i];
    }
}

// ---------------- TF32 mma.sync GEMM, fp16 output ----------

__device__ __forceinline__ const float* src_buf(int id, const float* ext) {
    if (id == 1) return g_A;
    return ext;
}

__device__ __forceinline__ float ftf32(float x) {
    float y;
    asm("cvt.rna.tf32.f32 %0, %1;" : "=f"(y) : "f"(x));
    return y;
}

#define BM  128
#define BN  128
#define BK  16
#define ASTR 20     // As row stride (floats): conflict-free for frag reads
#define BSTR 136    // Bs row stride (floats): conflict-free for frag reads

// C[m][n] = sum_k A[m][k]*B[k][n] + bias[n]; C -> g_H as __half2, pitch ldc2 half2
__global__ __launch_bounds__(256, 1) void gemm_mma_kernel(
    const float* __restrict__ Aext, int a_id, int lda,
    const float* __restrict__ B, int ldb,
    const float* __restrict__ bias,
    int ldc2, int M, int Nn, int K)
{
    __shared__ float As[2][BM][ASTR];
    __shared__ float Bs[2][BK][BSTR];
    __shared__ float sbias[BN];

    const float* A = src_buf(a_id, Aext);
    __half2* C2 = (__half2*)g_H;

    int tid = threadIdx.x, wid = tid >> 5, lane = tid & 31;
    int g = lane >> 2, tig = lane & 3;
    int wr = wid & 3, wc = wid >> 2;            // 4x2 warp grid
    int m0 = blockIdx.y * BM, n0 = blockIdx.x * BN;

    if (tid < BN) {
        sbias[tid] = (n0 + tid < Nn) ? bias[n0 + tid] : 0.f;
    }

    float acc[2][8][4];
    #pragma unroll
    for (int i = 0; i < 2; i++)
        #pragma unroll
        for (int j = 0; j < 8; j++)
            #pragma unroll
            for (int q = 0; q < 4; q++) acc[i][j][q] = 0.f;

    int nIter = (K + BK - 1) >> 4;

    // ---- preload chunk 0 into buffer 0 ----
    {
        int k0 = 0;
        #pragma unroll
        for (int p = 0; p < 2; ++p) {           // A: 512 float4 / 256 thr
            int f = p * 256 + tid;
            int r = f >> 2, c4 = f & 3;
            int gm = m0 + r;
            float v[4] = {0.f, 0.f, 0.f, 0.f};
            if (gm < M) {
                if (k0 + 16 <= K) {
                    float4 t = *(const float4*)&A[(size_t)gm * lda + k0 + c4 * 4];
                    v[0] = t.x; v[1] = t.y; v[2] = t.z; v[3] = t.w;
                } else {
                    #pragma unroll
                    for (int e = 0; e < 4; ++e) {
                        int gk = k0 + c4 * 4 + e;
                        if (gk < K) v[e] = A[(size_t)gm * lda + gk];
                    }
                }
            }
            #pragma unroll
            for (int e = 0; e < 4; ++e) As[0][r][c4 * 4 + e] = ftf32(v[e]);
        }
        #pragma unroll
        for (int p = 0; p < 8; ++p) {           // B: 2048 floats / 256 thr
            int e = p * 256 + tid;
            int r = e >> 7, c = e & 127;
            int gk = k0 + r, gn = n0 + c;
            float v = (gk < K && gn < Nn) ? B[(size_t)gk * ldb + gn] : 0.f;
            Bs[0][r][c] = ftf32(v);
        }
    }
    __syncthreads();

    int buf = 0;
    for (int it = 0; it < nIter; ++it) {
        bool hasNext = (it + 1) < nIter;
        int k1 = (it + 1) << 4;
        float ra[2][4];
        float rb[8];
        if (hasNext) {
            #pragma unroll
            for (int p = 0; p < 2; ++p) {
                int f = p * 256 + tid;
                int r = f >> 2, c4 = f & 3;
                int gm = m0 + r;
                ra[p][0] = ra[p][1] = ra[p][2] = ra[p][3] = 0.f;
                if (gm < M) {
                    if (k1 + 16 <= K) {
                        float4 t = *(const float4*)&A[(size_t)gm * lda + k1 + c4 * 4];
                        ra[p][0] = t.x; ra[p][1] = t.y; ra[p][2] = t.z; ra[p][3] = t.w;
                    } else {
                        #pragma unroll
                        for (int e = 0; e < 4; ++e) {
                            int gk = k1 + c4 * 4 + e;
                            if (gk < K) ra[p][e] = A[(size_t)gm * lda + gk];
                        }
                    }
                }
            }
            #pragma unroll
            for (int p = 0; p < 8; ++p) {
                int e = p * 256 + tid;
                int r = e >> 7, c = e & 127;
                int gk = k1 + r, gn = n0 + c;
                rb[p] = (gk < K && gn < Nn) ? B[(size_t)gk * ldb + gn] : 0.f;
            }
        }

        #pragma unroll
        for (int kk = 0; kk < BK; kk += 8) {
            uint32_t af[2][4];
            #pragma unroll
            for (int i = 0; i < 2; ++i) {
                int rA = wr * 32 + i * 16;
                af[i][0] = __float_as_uint(As[buf][rA + g    ][kk + tig    ]);
                af[i][1] = __float_as_uint(As[buf][rA + g + 8][kk + tig    ]);
                af[i][2] = __float_as_uint(As[buf][rA + g    ][kk + tig + 4]);
                af[i][3] = __float_as_uint(As[buf][rA + g + 8][kk + tig + 4]);
            }
            uint32_t bf[8][2];
            #pragma unroll
            for (int j = 0; j < 8; ++j) {
                int cB = wc * 64 + j * 8 + g;
                bf[j][0] = __float_as_uint(Bs[buf][kk + tig    ][cB]);
                bf[j][1] = __float_as_uint(Bs[buf][kk + tig + 4][cB]);
            }
            #pragma unroll
            for (int i = 0; i < 2; ++i)
                #pragma unroll
                for (int j = 0; j < 8; ++j) {
                    asm volatile(
                        "mma.sync.aligned.m16n8k8.row.col.f32.tf32.tf32.f32 "
                        "{%0,%1,%2,%3}, {%4,%5,%6,%7}, {%8,%9}, {%0,%1,%2,%3};"
                        : "+f"(acc[i][j][0]), "+f"(acc[i][j][1]),
                          "+f"(acc[i][j][2]), "+f"(acc[i][j][3])
                        : "r"(af[i][0]), "r"(af[i][1]), "r"(af[i][2]), "r"(af[i][3]),
                          "r"(bf[j][0]), "r"(bf[j][1]));
                }
        }

        if (hasNext) {
            int nb = buf ^ 1;
            #pragma unroll
            for (int p = 0; p < 2; ++p) {
                int f = p * 256 + tid;
                int r = f >> 2, c4 = f & 3;
                #pragma unroll
                for (int e = 0; e < 4; ++e) As[nb][r][c4 * 4 + e] = ftf32(ra[p][e]);
            }
            #pragma unroll
            for (int p = 0; p < 8; ++p) {
                int e = p * 256 + tid;
                int r = e >> 7, c = e & 127;
                Bs[nb][r][c] = ftf32(rb[p]);
            }
        }
        __syncthreads();
        buf ^= 1;
    }

    // ---- epilogue: bias add, half2 stores ----
    #pragma unroll
    for (int i = 0; i < 2; ++i) {
        int r0 = m0 + wr * 32 + i * 16 + g;
        int r1 = r0 + 8;
        #pragma unroll
        for (int j = 0; j < 8; ++j) {
            int nn = n0 + wc * 64 + j * 8 + 2 * tig;   // always even
            if (nn < Nn) {
                float b0 = sbias[wc * 64 + j * 8 + 2 * tig];
                float b1 = sbias[wc * 64 + j * 8 + 2 * tig + 1];
                if (r0 < M)
                    C2[(size_t)r0 * ldc2 + (nn >> 1)] =
                        __floats2half2_rn(acc[i][j][0] + b0, acc[i][j][1] + b1);
                if (r1 < M)
                    C2[(size_t)r1 * ldc2 + (nn >> 1)] =
                        __floats2half2_rn(acc[i][j][2] + b0, acc[i][j][3] + b1);
            }
        }
    }
}

// ---------------- SpMM over fp16 features (warp/row, uint4 gathers) + tanh --

// Layer 1: 500 features as half, pitch 512 halves (= 64 uint4); out fp32 pitch 512
__global__ __launch_bounds__(256) void spmm1_tanh_h_kernel(int n)
{
    const uint4* Hh = (const uint4*)g_H;       // 8 halves per uint4
    float* Out = g_A;

    int gw = (blockIdx.x * blockDim.x + threadIdx.x) >> 5;
    if (gw >= n) return;
    int lane = threadIdx.x & 31;

    float2 acc[2][4];
    #pragma unroll
    for (int q = 0; q < 2; ++q)
        #pragma unroll
        for (int p = 0; p < 4; ++p) acc[q][p] = make_float2(0.f, 0.f);

    int s = g_rowptr[gw], e = g_rowptr[gw + 1];
    for (int j = s; j < e; ++j) {
        int   c  = __ldg(&g_colidx[j]);
        float wj = __ldg(&g_wnorm[j]);
        const uint4* base = Hh + (size_t)c * 64;
        #pragma unroll
        for (int q = 0; q < 2; ++q) {
            int idx = lane + 32 * q;
            if (idx < 63) {                    // 63 uint4 cover 504 >= 500 halves
                uint4 v = base[idx];
                #pragma unroll
                for (int p = 0; p < 4; ++p) {
                    float2 f = __half22float2(*(const __half2*)((&v.x) + p));
                    acc[q][p].x += wj * f.x;
                    acc[q][p].y += wj * f.y;
                }
            }
        }
    }
    #pragma unroll
    for (int q = 0; q < 2; ++q) {
        int idx = lane + 32 * q;
        if (idx < 63) {
            #pragma unroll
            for (int p = 0; p < 4; ++p) {
                int col = 8 * idx + 2 * p;
                if (col < 500) {
                    float2 t = make_float2(tanhf(acc[q][p].x), tanhf(acc[q][p].y));
                    *(float2*)&Out[(size_t)gw * 512 + col] = t;
                }
            }
        }
    }
}

// Layer 2: 100 features as half, pitch 128 halves (= 64 half2); out fp32 pitch 128
__global__ __launch_bounds__(256) void spmm2_tanh_h_kernel(int n)
{
    const __half2* Hh = (const __half2*)g_H;
    float* Out = g_A;

    int gw = (blockIdx.x * blockDim.x + threadIdx.x) >> 5;
    if (gw >= n) return;
    int lane = threadIdx.x & 31;

    float2 acc[2];
    acc[0] = make_float2(0.f, 0.f);
    acc[1] = make_float2(0.f, 0.f);

    int s = g_rowptr[gw], e = g_rowptr[gw + 1];
    for (int j = s; j < e; ++j) {
        int   c  = __ldg(&g_colidx[j]);
        float wj = __ldg(&g_wnorm[j]);
        const __half2* base = Hh + (size_t)c * 64;
        #pragma unroll
        for (int q = 0; q < 2; ++q) {
            int idx = lane + 32 * q;
            if (idx < 50) {                    // 50 half2 = 100 halves
                float2 f = __half22float2(base[idx]);
                acc[q].x += wj * f.x;
                acc[q].y += wj * f.y;
            }
        }
    }
    #pragma unroll
    for (int q = 0; q < 2; ++q) {
        int idx = lane + 32 * q;
        if (idx < 50) {
            float2 t = make_float2(tanhf(acc[q].x), tanhf(acc[q].y));
            *(float2*)&Out[(size_t)gw * 128 + 2 * idx] = t;
        }
    }
}

// ---------------- layer 3: tiny GEMM + fused SpMM/tanh/softmax --------------

__global__ __launch_bounds__(256) void gemm3_kernel(
    const float* __restrict__ W3, const float* __restrict__ b3, int n)
{
    __shared__ float Ws[H2D * NCLS];
    __shared__ float bs[NCLS];
    for (int i = threadIdx.x; i < H2D * NCLS; i += 256) Ws[i] = W3[i];
    if (threadIdx.x < NCLS) bs[threadIdx.x] = b3[threadIdx.x];
    __syncthreads();

    int row = blockIdx.x * blockDim.x + threadIdx.x;
    if (row >= n) return;
    float acc[NCLS];
    #pragma unroll
    for (int j = 0; j < NCLS; j++) acc[j] = bs[j];
    const float* a = g_A + (size_t)row * 128;
    for (int k = 0; k < H2D; ++k) {
        float av = a[k];
        #pragma unroll
        for (int j = 0; j < NCLS; j++) acc[j] += av * Ws[k * NCLS + j];
    }
    float* o = g_H + (size_t)row * NCLS;
    #pragma unroll
    for (int j = 0; j < NCLS; j++) o[j] = acc[j];
}

__global__ __launch_bounds__(256) void spmm3_softmax_kernel(float* __restrict__ out, int n)
{
    int row = blockIdx.x * blockDim.x + threadIdx.x;
    if (row >= n) return;
    float acc[NCLS];
    #pragma unroll
    for (int j = 0; j < NCLS; j++) acc[j] = 0.f;

    int s = g_rowptr[row], e = g_rowptr[row + 1];
    for (int j = s; j < e; ++j) {
        int   c  = g_colidx[j];
        float wj = g_wnorm[j];
        const float4* b = (const float4*)(g_H + (size_t)c * NCLS);
        #pragma unroll
        for (int q = 0; q < 4; ++q) {
            float4 v = b[q];
            acc[4 * q + 0] += wj * v.x; acc[4 * q + 1] += wj * v.y;
            acc[4 * q + 2] += wj * v.z; acc[4 * q + 3] += wj * v.w;
        }
    }
    float mx = -1e30f;
    #pragma unroll
    for (int j = 0; j < NCLS; j++) { acc[j] = tanhf(acc[j]); mx = fmaxf(mx, acc[j]); }
    float sum = 0.f;
    #pragma unroll
    for (int j = 0; j < NCLS; j++) { acc[j] = expf(acc[j] - mx); sum += acc[j]; }
    float inv = 1.f / sum;
    float* o = out + (size_t)row * NCLS;
    #pragma unroll
    for (int j = 0; j < NCLS; j++) o[j] = acc[j] * inv;
}

// ---------------- launch ----------------

extern "C" void kernel_launch(void* const* d_in, const int* in_sizes, int n_in,
                              void* d_out, int out_size)
{
    const float* x  = (const float*)d_in[0];
    const void*  ei = d_in[1];
    const float* W1 = (const float*)d_in[2];
    const float* b1 = (const float*)d_in[3];
    const float* W2 = (const float*)d_in[4];
    const float* b2 = (const float*)d_in[5];
    const float* W3 = (const float*)d_in[6];
    const float* b3 = (const float*)d_in[7];
    float* out = (float*)d_out;

    int n = in_sizes[0] / F_IN;   // 50000
    int E = in_sizes[1] / 2;      // 800000

    // --- CSR build ---
    detect_dtype_kernel<<<1, 256>>>((const long long*)ei);
    init_deg_kernel<<<(n + 255) / 256, 256>>>(n);
    hist_kernel<<<(E + 255) / 256, 256>>>(ei, E);
    dinv_kernel<<<(n + 255) / 256, 256>>>(n);
    scan_kernel<<<1, 1024>>>(n);
    fill_kernel<<<(E + n + 255) / 256, 256>>>(ei, E, n);

    // --- layer 1: TF32 GEMM [N,512]x[512,500] -> g_H half (pitch 512h), SpMM+tanh -> g_A fp32
    {
        dim3 g((H1D + BN - 1) / BN, (n + BM - 1) / BM);
        gemm_mma_kernel<<<g, 256>>>(x, 2, F_IN, W1, H1D, b1, 256, n, H1D, F_IN);
    }
    spmm1_tanh_h_kernel<<<(n * 32 + 255) / 256, 256>>>(n);

    // --- layer 2: TF32 GEMM [N,500]x[500,100] -> g_H half (pitch 128h), SpMM+tanh -> g_A fp32
    {
        dim3 g((H2D + BN - 1) / BN, (n + BM - 1) / BM);
        gemm_mma_kernel<<<g, 256>>>(nullptr, 1, 512, W2, H2D, b2, 64, n, H2D, H1D);
    }
    spmm2_tanh_h_kernel<<<(n * 32 + 255) / 256, 256>>>(n);

    // --- layer 3: tiny GEMM -> g_H fp32 (pitch 16), fused SpMM+tanh+softmax -> out
    gemm3_kernel<<<(n + 255) / 256, 256>>>(W3, b3, n);
    spmm3_softmax_kernel<<<(n + 255) / 256, 256>>>(out, n);
}

// round 6
// speedup vs baseline: 1.9256x; 1.0874x over previous
#include <cuda_runtime.h>
#include <cuda_fp16.h>
#include <math.h>
#include <stdint.h>

#define N_NODES 50000
#define F_IN    512
#define H1D     500
#define H2D     100
#define NCLS    16

// ---------------- device scratch (no allocations allowed) ----------------
__device__ __align__(16) float g_H[(size_t)N_NODES * 512];   // half for L1/L2 GEMM out, fp32 for gemm3
__device__ __align__(16) float g_A[(size_t)N_NODES * 512];   // half for spmm1 out, fp32 for spmm2 out
__device__ int   g_deg[N_NODES];
__device__ float g_dinv[N_NODES];
__device__ int   g_rowptr[N_NODES + 1];
__device__ int   g_cursor[N_NODES];
__device__ int   g_colidx[800000 + N_NODES];
__device__ float g_wnorm[800000 + N_NODES];
__device__ int   g_is64;

// ---------------- graph preprocessing (unchanged, passing) ---------

__global__ void detect_dtype_kernel(const long long* __restrict__ ei) {
    __shared__ int bad;
    if (threadIdx.x == 0) bad = 0;
    __syncthreads();
    #pragma unroll
    for (int i = 0; i < 4; ++i) {
        long long v = ei[threadIdx.x * 4 + i];
        if (v < 0 || v >= (long long)N_NODES) bad = 1;
    }
    __syncthreads();
    if (threadIdx.x == 0) g_is64 = bad ? 0 : 1;
}

__global__ void init_deg_kernel(int n) {
    int i = blockIdx.x * blockDim.x + threadIdx.x;
    if (i < n) g_deg[i] = 1;
}

__global__ void hist_kernel(const void* __restrict__ ei, int E) {
    int e = blockIdx.x * blockDim.x + threadIdx.x;
    if (e >= E) return;
    int r = g_is64 ? (int)((const long long*)ei)[e] : ((const int*)ei)[e];
    atomicAdd(&g_deg[r], 1);
}

__global__ void dinv_kernel(int n) {
    int i = blockIdx.x * blockDim.x + threadIdx.x;
    if (i < n) g_dinv[i] = rsqrtf((float)g_deg[i]);
}

__global__ void scan_kernel(int n) {
    __shared__ int ssum[1024];
    int t = threadIdx.x;
    int ch = (n + 1023) >> 10;
    int lo = t * ch;
    int hi = min(lo + ch, n);
    int s = 0;
    for (int i = lo; i < hi; ++i) s += g_deg[i];
    ssum[t] = s;
    __syncthreads();
    for (int off = 1; off < 1024; off <<= 1) {
        int v = (t >= off) ? ssum[t - off] : 0;
        __syncthreads();
        ssum[t] += v;
        __syncthreads();
    }
    int run = (t == 0) ? 0 : ssum[t - 1];
    for (int i = lo; i < hi; ++i) {
        g_rowptr[i] = run;
        g_cursor[i] = run;
        run += g_deg[i];
    }
    if (t == 1023) g_rowptr[n] = ssum[1023];
}

__global__ void fill_kernel(const void* __restrict__ ei, int E, int n) {
    int t = blockIdx.x * blockDim.x + threadIdx.x;
    if (t < E) {
        int r, c;
        if (g_is64) {
            r = (int)((const long long*)ei)[t];
            c = (int)((const long long*)ei)[E + t];
        } else {
            r = ((const int*)ei)[t];
            c = ((const int*)ei)[E + t];
        }
        int pos = atomicAdd(&g_cursor[r], 1);
        g_colidx[pos] = c;
        g_wnorm[pos]  = g_dinv[r] * g_dinv[c];
    } else if (t < E + n) {
        int i = t - E;
        int pos = atomicAdd(&g_cursor[i], 1);
        g_colidx[pos] = i;
        g_wnorm[pos]  = g_dinv[i] * g_dinv[i];
    }
}

// ---------------- FP16 mma.sync GEMM (m16n8k16), fp16 output ----------

#define BM  128
#define BN  128
#define BK  16
#define ASTR2 12    // As row stride in half2: frag addr 12g+tig distinct mod 32
#define BSTR2 136   // Bs row stride in half2: frag addr 8*tig+g distinct mod 32

// C[m][n] = sum_k A[m][k]*B[k][n] + bias[n]; C -> g_H as __half2, pitch ldc2 half2
// a_id: 1 => A = g_A as half (lda in halves); 2 => A = Aext fp32 (lda in floats)
__global__ __launch_bounds__(256, 1) void gemm_mma_kernel(
    const float* __restrict__ Aext, int a_id, int lda,
    const float* __restrict__ B, int ldb,
    const float* __restrict__ bias,
    int ldc2, int M, int Nn, int K)
{
    __shared__ __half2 As2[2][BM][ASTR2];   // cols 0..7 used (16 halves)
    __shared__ __half2 Bs2[2][BK / 2][BSTR2];
    __shared__ float sbias[BN];

    const float*  Af = (a_id == 2) ? Aext : nullptr;
    const __half* Ah = (a_id == 1) ? (const __half*)g_A : nullptr;
    __half2* C2 = (__half2*)g_H;

    int tid = threadIdx.x, wid = tid >> 5, lane = tid & 31;
    int g = lane >> 2, tig = lane & 3;
    int wr = wid & 3, wc = wid >> 2;            // 4x2 warp grid
    int m0 = blockIdx.y * BM, n0 = blockIdx.x * BN;

    if (tid < BN) {
        sbias[tid] = (n0 + tid < Nn) ? bias[n0 + tid] : 0.f;
    }

    float acc[2][8][4];
    #pragma unroll
    for (int i = 0; i < 2; i++)
        #pragma unroll
        for (int j = 0; j < 8; j++)
            #pragma unroll
            for (int q = 0; q < 4; q++) acc[i][j][q] = 0.f;

    int nIter = (K + BK - 1) >> 4;

    // ---- stage helpers inline: chunk k0 -> buffer bb ----
    // A: 2 passes, each thread handles (row r, half2 cols 2c4, 2c4+1)
    // B: 4 passes, each thread handles one half2 (k-pair row r, col c)

    // preload chunk 0
    {
        int k0 = 0;
        #pragma unroll
        for (int p = 0; p < 2; ++p) {
            int f = p * 256 + tid;
            int r = f >> 2, c4 = f & 3;
            int gm = m0 + r;
            float v[4] = {0.f, 0.f, 0.f, 0.f};
            if (gm < M) {
                if (a_id == 2) {
                    if (k0 + 16 <= K) {
                        float4 t = *(const float4*)&Af[(size_t)gm * lda + k0 + c4 * 4];
                        v[0] = t.x; v[1] = t.y; v[2] = t.z; v[3] = t.w;
                    } else {
                        #pragma unroll
                        for (int e = 0; e < 4; ++e) {
                            int gk = k0 + c4 * 4 + e;
                            if (gk < K) v[e] = Af[(size_t)gm * lda + gk];
                        }
                    }
                } else {
                    if (k0 + 16 <= K) {
                        uint2 t = *(const uint2*)&Ah[(size_t)gm * lda + k0 + c4 * 4];
                        __half2 h0 = *(__half2*)&t.x, h1 = *(__half2*)&t.y;
                        float2 f0 = __half22float2(h0), f1 = __half22float2(h1);
                        v[0] = f0.x; v[1] = f0.y; v[2] = f1.x; v[3] = f1.y;
                    } else {
                        #pragma unroll
                        for (int e = 0; e < 4; ++e) {
                            int gk = k0 + c4 * 4 + e;
                            if (gk < K) v[e] = __half2float(Ah[(size_t)gm * lda + gk]);
                        }
                    }
                }
            }
            As2[0][r][2 * c4]     = __floats2half2_rn(v[0], v[1]);
            As2[0][r][2 * c4 + 1] = __floats2half2_rn(v[2], v[3]);
        }
        #pragma unroll
        for (int p = 0; p < 4; ++p) {
            int e = p * 256 + tid;
            int r = e >> 7, c = e & 127;
            int gk = k0 + 2 * r, gn = n0 + c;
            float v0 = (gk < K && gn < Nn) ? B[(size_t)gk * ldb + gn] : 0.f;
            float v1 = (gk + 1 < K && gn < Nn) ? B[(size_t)(gk + 1) * ldb + gn] : 0.f;
            Bs2[0][r][c] = __floats2half2_rn(v0, v1);
        }
    }
    __syncthreads();

    int buf = 0;
    for (int it = 0; it < nIter; ++it) {
        bool hasNext = (it + 1) < nIter;
        int k1 = (it + 1) << 4;
        float ra[2][4];
        float rb[4][2];
        if (hasNext) {
            #pragma unroll
            for (int p = 0; p < 2; ++p) {
                int f = p * 256 + tid;
                int r = f >> 2, c4 = f & 3;
                int gm = m0 + r;
                ra[p][0] = ra[p][1] = ra[p][2] = ra[p][3] = 0.f;
                if (gm < M) {
                    if (a_id == 2) {
                        if (k1 + 16 <= K) {
                            float4 t = *(const float4*)&Af[(size_t)gm * lda + k1 + c4 * 4];
                            ra[p][0] = t.x; ra[p][1] = t.y; ra[p][2] = t.z; ra[p][3] = t.w;
                        } else {
                            #pragma unroll
                            for (int e = 0; e < 4; ++e) {
                                int gk = k1 + c4 * 4 + e;
                                if (gk < K) ra[p][e] = Af[(size_t)gm * lda + gk];
                            }
                        }
                    } else {
                        if (k1 + 16 <= K) {
                            uint2 t = *(const uint2*)&Ah[(size_t)gm * lda + k1 + c4 * 4];
                            __half2 h0 = *(__half2*)&t.x, h1 = *(__half2*)&t.y;
                            float2 f0 = __half22float2(h0), f1 = __half22float2(h1);
                            ra[p][0] = f0.x; ra[p][1] = f0.y; ra[p][2] = f1.x; ra[p][3] = f1.y;
                        } else {
                            #pragma unroll
                            for (int e = 0; e < 4; ++e) {
                                int gk = k1 + c4 * 4 + e;
                                if (gk < K) ra[p][e] = __half2float(Ah[(size_t)gm * lda + gk]);
                            }
                        }
                    }
                }
            }
            #pragma unroll
            for (int p = 0; p < 4; ++p) {
                int e = p * 256 + tid;
                int r = e >> 7, c = e & 127;
                int gk = k1 + 2 * r, gn = n0 + c;
                rb[p][0] = (gk < K && gn < Nn) ? B[(size_t)gk * ldb + gn] : 0.f;
                rb[p][1] = (gk + 1 < K && gn < Nn) ? B[(size_t)(gk + 1) * ldb + gn] : 0.f;
            }
        }

        // ---- one m16n8k16 MMA sweep covers the whole BK=16 chunk ----
        {
            uint32_t af[2][4];
            #pragma unroll
            for (int i = 0; i < 2; ++i) {
                int rA = wr * 32 + i * 16;
                af[i][0] = *(const uint32_t*)&As2[buf][rA + g    ][tig    ];
                af[i][1] = *(const uint32_t*)&As2[buf][rA + g + 8][tig    ];
                af[i][2] = *(const uint32_t*)&As2[buf][rA + g    ][tig + 4];
                af[i][3] = *(const uint32_t*)&As2[buf][rA + g + 8][tig + 4];
            }
            uint32_t bf[8][2];
            #pragma unroll
            for (int j = 0; j < 8; ++j) {
                int cB = wc * 64 + j * 8 + g;
                bf[j][0] = *(const uint32_t*)&Bs2[buf][tig    ][cB];
                bf[j][1] = *(const uint32_t*)&Bs2[buf][tig + 4][cB];
            }
            #pragma unroll
            for (int i = 0; i < 2; ++i)
                #pragma unroll
                for (int j = 0; j < 8; ++j) {
                    asm volatile(
                        "mma.sync.aligned.m16n8k16.row.col.f32.f16.f16.f32 "
                        "{%0,%1,%2,%3}, {%4,%5,%6,%7}, {%8,%9}, {%0,%1,%2,%3};"
                        : "+f"(acc[i][j][0]), "+f"(acc[i][j][1]),
                          "+f"(acc[i][j][2]), "+f"(acc[i][j][3])
                        : "r"(af[i][0]), "r"(af[i][1]), "r"(af[i][2]), "r"(af[i][3]),
                          "r"(bf[j][0]), "r"(bf[j][1]));
                }
        }

        if (hasNext) {
            int nb = buf ^ 1;
            #pragma unroll
            for (int p = 0; p < 2; ++p) {
                int f = p * 256 + tid;
                int r = f >> 2, c4 = f & 3;
                As2[nb][r][2 * c4]     = __floats2half2_rn(ra[p][0], ra[p][1]);
                As2[nb][r][2 * c4 + 1] = __floats2half2_rn(ra[p][2], ra[p][3]);
            }
            #pragma unroll
            for (int p = 0; p < 4; ++p) {
                int e = p * 256 + tid;
                int r = e >> 7, c = e & 127;
                Bs2[nb][r][c] = __floats2half2_rn(rb[p][0], rb[p][1]);
            }
        }
        __syncthreads();
        buf ^= 1;
    }

    // ---- epilogue: bias add, half2 stores ----
    #pragma unroll
    for (int i = 0; i < 2; ++i) {
        int r0 = m0 + wr * 32 + i * 16 + g;
        int r1 = r0 + 8;
        #pragma unroll
        for (int j = 0; j < 8; ++j) {
            int nn = n0 + wc * 64 + j * 8 + 2 * tig;   // always even
            if (nn < Nn) {
                float b0 = sbias[wc * 64 + j * 8 + 2 * tig];
                float b1 = sbias[wc * 64 + j * 8 + 2 * tig + 1];
                if (r0 < M)
                    C2[(size_t)r0 * ldc2 + (nn >> 1)] =
                        __floats2half2_rn(acc[i][j][0] + b0, acc[i][j][1] + b1);
                if (r1 < M)
                    C2[(size_t)r1 * ldc2 + (nn >> 1)] =
                        __floats2half2_rn(acc[i][j][2] + b0, acc[i][j][3] + b1);
            }
        }
    }
}

// ---------------- SpMM over fp16 features (warp/row, uint4 gathers) + tanh --

// Layer 1: 500 half features, pitch 512 halves (= 64 uint4); out HALF pitch 512
__global__ __launch_bounds__(256) void spmm1_tanh_h_kernel(int n)
{
    const uint4* Hh = (const uint4*)g_H;       // 8 halves per uint4
    __half2* Out2 = (__half2*)g_A;

    int gw = (blockIdx.x * blockDim.x + threadIdx.x) >> 5;
    if (gw >= n) return;
    int lane = threadIdx.x & 31;

    float2 acc[2][4];
    #pragma unroll
    for (int q = 0; q < 2; ++q)
        #pragma unroll
        for (int p = 0; p < 4; ++p) acc[q][p] = make_float2(0.f, 0.f);

    int s = g_rowptr[gw], e = g_rowptr[gw + 1];
    for (int j = s; j < e; ++j) {
        int   c  = __ldg(&g_colidx[j]);
        float wj = __ldg(&g_wnorm[j]);
        const uint4* base = Hh + (size_t)c * 64;
        #pragma unroll
        for (int q = 0; q < 2; ++q) {
            int idx = lane + 32 * q;
            if (idx < 63) {                    // 63 uint4 cover 504 >= 500 halves
                uint4 v = base[idx];
                #pragma unroll
                for (int p = 0; p < 4; ++p) {
                    float2 f = __half22float2(*(const __half2*)((&v.x) + p));
                    acc[q][p].x += wj * f.x;
                    acc[q][p].y += wj * f.y;
                }
            }
        }
    }
    #pragma unroll
    for (int q = 0; q < 2; ++q) {
        int idx = lane + 32 * q;
        if (idx < 63) {
            #pragma unroll
            for (int p = 0; p < 4; ++p) {
                int col = 8 * idx + 2 * p;
                if (col < 500) {
                    Out2[(size_t)gw * 256 + (col >> 1)] =
                        __floats2half2_rn(tanhf(acc[q][p].x), tanhf(acc[q][p].y));
                }
            }
        }
    }
}

// Layer 2: 100 half features, pitch 128 halves (= 64 half2); out fp32 pitch 128
__global__ __launch_bounds__(256) void spmm2_tanh_h_kernel(int n)
{
    const __half2* Hh = (const __half2*)g_H;
    float* Out = g_A;

    int gw = (blockIdx.x * blockDim.x + threadIdx.x) >> 5;
    if (gw >= n) return;
    int lane = threadIdx.x & 31;

    float2 acc[2];
    acc[0] = make_float2(0.f, 0.f);
    acc[1] = make_float2(0.f, 0.f);

    int s = g_rowptr[gw], e = g_rowptr[gw + 1];
    for (int j = s; j < e; ++j) {
        int   c  = __ldg(&g_colidx[j]);
        float wj = __ldg(&g_wnorm[j]);
        const __half2* base = Hh + (size_t)c * 64;
        #pragma unroll
        for (int q = 0; q < 2; ++q) {
            int idx = lane + 32 * q;
            if (idx < 50) {                    // 50 half2 = 100 halves
                float2 f = __half22float2(base[idx]);
                acc[q].x += wj * f.x;
                acc[q].y += wj * f.y;
            }
        }
    }
    #pragma unroll
    for (int q = 0; q < 2; ++q) {
        int idx = lane + 32 * q;
        if (idx < 50) {
            float2 t = make_float2(tanhf(acc[q].x), tanhf(acc[q].y));
            *(float2*)&Out[(size_t)gw * 128 + 2 * idx] = t;
        }
    }
}

// ---------------- layer 3: tiny GEMM + fused SpMM/tanh/softmax --------------

__global__ __launch_bounds__(256) void gemm3_kernel(
    const float* __restrict__ W3, const float* __restrict__ b3, int n)
{
    __shared__ float Ws[H2D * NCLS];
    __shared__ float bs[NCLS];
    for (int i = threadIdx.x; i < H2D * NCLS; i += 256) Ws[i] = W3[i];
    if (threadIdx.x < NCLS) bs[threadIdx.x] = b3[threadIdx.x];
    __syncthreads();

    int row = blockIdx.x * blockDim.x + threadIdx.x;
    if (row >= n) return;
    float acc[NCLS];
    #pragma unroll
    for (int j = 0; j < NCLS; j++) acc[j] = bs[j];
    const float* a = g_A + (size_t)row * 128;
    for (int k = 0; k < H2D; ++k) {
        float av = a[k];
        #pragma unroll
        for (int j = 0; j < NCLS; j++) acc[j] += av * Ws[k * NCLS + j];
    }
    float* o = g_H + (size_t)row * NCLS;
    #pragma unroll
    for (int j = 0; j < NCLS; j++) o[j] = acc[j];
}

__global__ __launch_bounds__(256) void spmm3_softmax_kernel(float* __restrict__ out, int n)
{
    int row = blockIdx.x * blockDim.x + threadIdx.x;
    if (row >= n) return;
    float acc[NCLS];
    #pragma unroll
    for (int j = 0; j < NCLS; j++) acc[j] = 0.f;

    int s = g_rowptr[row], e = g_rowptr[row + 1];
    for (int j = s; j < e; ++j) {
        int   c  = g_colidx[j];
        float wj = g_wnorm[j];
        const float4* b = (const float4*)(g_H + (size_t)c * NCLS);
        #pragma unroll
        for (int q = 0; q < 4; ++q) {
            float4 v = b[q];
            acc[4 * q + 0] += wj * v.x; acc[4 * q + 1] += wj * v.y;
            acc[4 * q + 2] += wj * v.z; acc[4 * q + 3] += wj * v.w;
        }
    }
    float mx = -1e30f;
    #pragma unroll
    for (int j = 0; j < NCLS; j++) { acc[j] = tanhf(acc[j]); mx = fmaxf(mx, acc[j]); }
    float sum = 0.f;
    #pragma unroll
    for (int j = 0; j < NCLS; j++) { acc[j] = expf(acc[j] - mx); sum += acc[j]; }
    float inv = 1.f / sum;
    float* o = out + (size_t)row * NCLS;
    #pragma unroll
    for (int j = 0; j < NCLS; j++) o[j] = acc[j] * inv;
}

// ---------------- launch ----------------

extern "C" void kernel_launch(void* const* d_in, const int* in_sizes, int n_in,
                              void* d_out, int out_size)
{
    const float* x  = (const float*)d_in[0];
    const void*  ei = d_in[1];
    const float* W1 = (const float*)d_in[2];
    const float* b1 = (const float*)d_in[3];
    const float* W2 = (const float*)d_in[4];
    const float* b2 = (const float*)d_in[5];
    const float* W3 = (const float*)d_in[6];
    const float* b3 = (const float*)d_in[7];
    float* out = (float*)d_out;

    int n = in_sizes[0] / F_IN;   // 50000
    int E = in_sizes[1] / 2;      // 800000

    // --- CSR build ---
    detect_dtype_kernel<<<1, 256>>>((const long long*)ei);
    init_deg_kernel<<<(n + 255) / 256, 256>>>(n);
    hist_kernel<<<(E + 255) / 256, 256>>>(ei, E);
    dinv_kernel<<<(n + 255) / 256, 256>>>(n);
    scan_kernel<<<1, 1024>>>(n);
    fill_kernel<<<(E + n + 255) / 256, 256>>>(ei, E, n);

    // --- layer 1: FP16 GEMM [N,512]x[512,500] -> g_H half (pitch 512h), SpMM+tanh -> g_A half
    {
        dim3 g((H1D + BN - 1) / BN, (n + BM - 1) / BM);
        gemm_mma_kernel<<<g, 256>>>(x, 2, F_IN, W1, H1D, b1, 256, n, H1D, F_IN);
    }
    spmm1_tanh_h_kernel<<<(n * 32 + 255) / 256, 256>>>(n);

    // --- layer 2: FP16 GEMM [N,500(half)]x[500,100] -> g_H half (pitch 128h), SpMM+tanh -> g_A fp32
    {
        dim3 g((H2D + BN - 1) / BN, (n + BM - 1) / BM);
        gemm_mma_kernel<<<g, 256>>>(nullptr, 1, 512, W2, H2D, b2, 64, n, H2D, H1D);
    }
    spmm2_tanh_h_kernel<<<(n * 32 + 255) / 256, 256>>>(n);

    // --- layer 3: tiny GEMM -> g_H fp32 (pitch 16), fused SpMM+tanh+softmax -> out
    gemm3_kernel<<<(n + 255) / 256, 256>>>(W3, b3, n);
    spmm3_softmax_kernel<<<(n + 255) / 256, 256>>>(out, n);
}

// round 7
// speedup vs baseline: 1.9981x; 1.0377x over previous
#include <cuda_runtime.h>
#include <cuda_fp16.h>
#include <math.h>
#include <stdint.h>

#define N_NODES 50000
#define F_IN    512
#define H1D     500
#define H2D     100
#define NCLS    16

// ---------------- device scratch (no allocations allowed) ----------------
__device__ __align__(16) float g_H[(size_t)N_NODES * 512];   // half for L1/L2 GEMM out, fp32 for gemm3
__device__ __align__(16) float g_A[(size_t)N_NODES * 512];   // half for spmm1 out, fp32 for spmm2 out
__device__ int   g_deg[N_NODES];
__device__ float g_dinv[N_NODES];
__device__ int   g_rowptr[N_NODES + 1];
__device__ int   g_cursor[N_NODES];
__device__ int   g_colidx[800000 + N_NODES];
__device__ float g_wnorm[800000 + N_NODES];
__device__ int   g_is64;

// ---------------- graph preprocessing ----------------

// block 0: dtype detect; blocks 1..: deg init (self loop)
__global__ void detect_init_kernel(const long long* __restrict__ ei, int n) {
    if (blockIdx.x == 0) {
        __shared__ int bad;
        if (threadIdx.x == 0) bad = 0;
        __syncthreads();
        #pragma unroll
        for (int i = 0; i < 4; ++i) {
            long long v = ei[threadIdx.x * 4 + i];
            if (v < 0 || v >= (long long)N_NODES) bad = 1;
        }
        __syncthreads();
        if (threadIdx.x == 0) g_is64 = bad ? 0 : 1;
    } else {
        int i = (blockIdx.x - 1) * blockDim.x + threadIdx.x;
        if (i < n) g_deg[i] = 1;
    }
}

__global__ void hist_kernel(const void* __restrict__ ei, int E) {
    int e = blockIdx.x * blockDim.x + threadIdx.x;
    if (e >= E) return;
    int r = g_is64 ? (int)((const long long*)ei)[e] : ((const int*)ei)[e];
    atomicAdd(&g_deg[r], 1);
}

__global__ void dinv_kernel(int n) {
    int i = blockIdx.x * blockDim.x + threadIdx.x;
    if (i < n) g_dinv[i] = rsqrtf((float)g_deg[i]);
}

__global__ void scan_kernel(int n) {
    __shared__ int ssum[1024];
    int t = threadIdx.x;
    int ch = (n + 1023) >> 10;
    int lo = t * ch;
    int hi = min(lo + ch, n);
    int s = 0;
    for (int i = lo; i < hi; ++i) s += g_deg[i];
    ssum[t] = s;
    __syncthreads();
    for (int off = 1; off < 1024; off <<= 1) {
        int v = (t >= off) ? ssum[t - off] : 0;
        __syncthreads();
        ssum[t] += v;
        __syncthreads();
    }
    int run = (t == 0) ? 0 : ssum[t - 1];
    for (int i = lo; i < hi; ++i) {
        g_rowptr[i] = run;
        g_cursor[i] = run;
        run += g_deg[i];
    }
    if (t == 1023) g_rowptr[n] = ssum[1023];
}

__global__ void fill_kernel(const void* __restrict__ ei, int E, int n) {
    int t = blockIdx.x * blockDim.x + threadIdx.x;
    if (t < E) {
        int r, c;
        if (g_is64) {
            r = (int)((const long long*)ei)[t];
            c = (int)((const long long*)ei)[E + t];
        } else {
            r = ((const int*)ei)[t];
            c = ((const int*)ei)[E + t];
        }
        int pos = atomicAdd(&g_cursor[r], 1);
        g_colidx[pos] = c;
        g_wnorm[pos]  = g_dinv[r] * g_dinv[c];
    } else if (t < E + n) {
        int i = t - E;
        int pos = atomicAdd(&g_cursor[i], 1);
        g_colidx[pos] = i;
        g_wnorm[pos]  = g_dinv[i] * g_dinv[i];
    }
}

// ---------------- FP16 mma.sync GEMM (m16n8k16), fp16 output ----------

#define BM  128
#define BN  128
#define BK  16
#define ASTR2 12    // As row stride in half2: frag addr 12g+tig distinct mod 32
#define BSTR2 136   // Bs row stride in half2: frag addr 8*tig+g distinct mod 32

// C[m][n] = sum_k A[m][k]*B[k][n] + bias[n]; C -> g_H as __half2, pitch ldc2 half2
// a_id: 1 => A = g_A as half (lda in halves); 2 => A = Aext fp32 (lda in floats)
__global__ __launch_bounds__(256, 1) void gemm_mma_kernel(
    const float* __restrict__ Aext, int a_id, int lda,
    const float* __restrict__ B, int ldb,
    const float* __restrict__ bias,
    int ldc2, int M, int Nn, int K)
{
    __shared__ __half2 As2[2][BM][ASTR2];   // cols 0..7 used (16 halves)
    __shared__ __half2 Bs2[2][BK / 2][BSTR2];
    __shared__ float sbias[BN];

    const float*  Af = (a_id == 2) ? Aext : nullptr;
    const __half* Ah = (a_id == 1) ? (const __half*)g_A : nullptr;
    __half2* C2 = (__half2*)g_H;

    int tid = threadIdx.x, wid = tid >> 5, lane = tid & 31;
    int g = lane >> 2, tig = lane & 3;
    int wr = wid & 3, wc = wid >> 2;            // 4x2 warp grid
    int m0 = blockIdx.y * BM, n0 = blockIdx.x * BN;

    if (tid < BN) {
        sbias[tid] = (n0 + tid < Nn) ? bias[n0 + tid] : 0.f;
    }

    float acc[2][8][4];
    #pragma unroll
    for (int i = 0; i < 2; i++)
        #pragma unroll
        for (int j = 0; j < 8; j++)
            #pragma unroll
            for (int q = 0; q < 4; q++) acc[i][j][q] = 0.f;

    int nIter = (K + BK - 1) >> 4;

    // preload chunk 0
    {
        int k0 = 0;
        #pragma unroll
        for (int p = 0; p < 2; ++p) {
            int f = p * 256 + tid;
            int r = f >> 2, c4 = f & 3;
            int gm = m0 + r;
            float v[4] = {0.f, 0.f, 0.f, 0.f};
            if (gm < M) {
                if (a_id == 2) {
                    if (k0 + 16 <= K) {
                        float4 t = *(const float4*)&Af[(size_t)gm * lda + k0 + c4 * 4];
                        v[0] = t.x; v[1] = t.y; v[2] = t.z; v[3] = t.w;
                    } else {
                        #pragma unroll
                        for (int e = 0; e < 4; ++e) {
                            int gk = k0 + c4 * 4 + e;
                            if (gk < K) v[e] = Af[(size_t)gm * lda + gk];
                        }
                    }
                } else {
                    if (k0 + 16 <= K) {
                        uint2 t = *(const uint2*)&Ah[(size_t)gm * lda + k0 + c4 * 4];
                        __half2 h0 = *(__half2*)&t.x, h1 = *(__half2*)&t.y;
                        float2 f0 = __half22float2(h0), f1 = __half22float2(h1);
                        v[0] = f0.x; v[1] = f0.y; v[2] = f1.x; v[3] = f1.y;
                    } else {
                        #pragma unroll
                        for (int e = 0; e < 4; ++e) {
                            int gk = k0 + c4 * 4 + e;
                            if (gk < K) v[e] = __half2float(Ah[(size_t)gm * lda + gk]);
                        }
                    }
                }
            }
            As2[0][r][2 * c4]     = __floats2half2_rn(v[0], v[1]);
            As2[0][r][2 * c4 + 1] = __floats2half2_rn(v[2], v[3]);
        }
        #pragma unroll
        for (int p = 0; p < 4; ++p) {
            int e = p * 256 + tid;
            int r = e >> 7, c = e & 127;
            int gk = k0 + 2 * r, gn = n0 + c;
            float v0 = (gk < K && gn < Nn) ? B[(size_t)gk * ldb + gn] : 0.f;
            float v1 = (gk + 1 < K && gn < Nn) ? B[(size_t)(gk + 1) * ldb + gn] : 0.f;
            Bs2[0][r][c] = __floats2half2_rn(v0, v1);
        }
    }
    __syncthreads();

    int buf = 0;
    for (int it = 0; it < nIter; ++it) {
        bool hasNext = (it + 1) < nIter;
        int k1 = (it + 1) << 4;
        float ra[2][4];
        float rb[4][2];
        if (hasNext) {
            #pragma unroll
            for (int p = 0; p < 2; ++p) {
                int f = p * 256 + tid;
                int r = f >> 2, c4 = f & 3;
                int gm = m0 + r;
                ra[p][0] = ra[p][1] = ra[p][2] = ra[p][3] = 0.f;
                if (gm < M) {
                    if (a_id == 2) {
                        if (k1 + 16 <= K) {
                            float4 t = *(const float4*)&Af[(size_t)gm * lda + k1 + c4 * 4];
                            ra[p][0] = t.x; ra[p][1] = t.y; ra[p][2] = t.z; ra[p][3] = t.w;
                        } else {
                            #pragma unroll
                            for (int e = 0; e < 4; ++e) {
                                int gk = k1 + c4 * 4 + e;
                                if (gk < K) ra[p][e] = Af[(size_t)gm * lda + gk];
                            }
                        }
                    } else {
                        if (k1 + 16 <= K) {
                            uint2 t = *(const uint2*)&Ah[(size_t)gm * lda + k1 + c4 * 4];
                            __half2 h0 = *(__half2*)&t.x, h1 = *(__half2*)&t.y;
                            float2 f0 = __half22float2(h0), f1 = __half22float2(h1);
                            ra[p][0] = f0.x; ra[p][1] = f0.y; ra[p][2] = f1.x; ra[p][3] = f1.y;
                        } else {
                            #pragma unroll
                            for (int e = 0; e < 4; ++e) {
                                int gk = k1 + c4 * 4 + e;
                                if (gk < K) ra[p][e] = __half2float(Ah[(size_t)gm * lda + gk]);
                            }
                        }
                    }
                }
            }
            #pragma unroll
            for (int p = 0; p < 4; ++p) {
                int e = p * 256 + tid;
                int r = e >> 7, c = e & 127;
                int gk = k1 + 2 * r, gn = n0 + c;
                rb[p][0] = (gk < K && gn < Nn) ? B[(size_t)gk * ldb + gn] : 0.f;
                rb[p][1] = (gk + 1 < K && gn < Nn) ? B[(size_t)(gk + 1) * ldb + gn] : 0.f;
            }
        }

        // ---- one m16n8k16 MMA sweep covers the whole BK=16 chunk ----
        {
            uint32_t af[2][4];
            #pragma unroll
            for (int i = 0; i < 2; ++i) {
                int rA = wr * 32 + i * 16;
                af[i][0] = *(const uint32_t*)&As2[buf][rA + g    ][tig    ];
                af[i][1] = *(const uint32_t*)&As2[buf][rA + g + 8][tig    ];
                af[i][2] = *(const uint32_t*)&As2[buf][rA + g    ][tig + 4];
                af[i][3] = *(const uint32_t*)&As2[buf][rA + g + 8][tig + 4];
            }
            uint32_t bf[8][2];
            #pragma unroll
            for (int j = 0; j < 8; ++j) {
                int cB = wc * 64 + j * 8 + g;
                bf[j][0] = *(const uint32_t*)&Bs2[buf][tig    ][cB];
                bf[j][1] = *(const uint32_t*)&Bs2[buf][tig + 4][cB];
            }
            #pragma unroll
            for (int i = 0; i < 2; ++i)
                #pragma unroll
                for (int j = 0; j < 8; ++j) {
                    asm volatile(
                        "mma.sync.aligned.m16n8k16.row.col.f32.f16.f16.f32 "
                        "{%0,%1,%2,%3}, {%4,%5,%6,%7}, {%8,%9}, {%0,%1,%2,%3};"
                        : "+f"(acc[i][j][0]), "+f"(acc[i][j][1]),
                          "+f"(acc[i][j][2]), "+f"(acc[i][j][3])
                        : "r"(af[i][0]), "r"(af[i][1]), "r"(af[i][2]), "r"(af[i][3]),
                          "r"(bf[j][0]), "r"(bf[j][1]));
                }
        }

        if (hasNext) {
            int nb = buf ^ 1;
            #pragma unroll
            for (int p = 0; p < 2; ++p) {
                int f = p * 256 + tid;
                int r = f >> 2, c4 = f & 3;
                As2[nb][r][2 * c4]     = __floats2half2_rn(ra[p][0], ra[p][1]);
                As2[nb][r][2 * c4 + 1] = __floats2half2_rn(ra[p][2], ra[p][3]);
            }
            #pragma unroll
            for (int p = 0; p < 4; ++p) {
                int e = p * 256 + tid;
                int r = e >> 7, c = e & 127;
                Bs2[nb][r][c] = __floats2half2_rn(rb[p][0], rb[p][1]);
            }
        }
        __syncthreads();
        buf ^= 1;
    }

    // ---- epilogue: bias add, half2 stores ----
    #pragma unroll
    for (int i = 0; i < 2; ++i) {
        int r0 = m0 + wr * 32 + i * 16 + g;
        int r1 = r0 + 8;
        #pragma unroll
        for (int j = 0; j < 8; ++j) {
            int nn = n0 + wc * 64 + j * 8 + 2 * tig;   // always even
            if (nn < Nn) {
                float b0 = sbias[wc * 64 + j * 8 + 2 * tig];
                float b1 = sbias[wc * 64 + j * 8 + 2 * tig + 1];
                if (r0 < M)
                    C2[(size_t)r0 * ldc2 + (nn >> 1)] =
                        __floats2half2_rn(acc[i][j][0] + b0, acc[i][j][1] + b1);
                if (r1 < M)
                    C2[(size_t)r1 * ldc2 + (nn >> 1)] =
                        __floats2half2_rn(acc[i][j][2] + b0, acc[i][j][3] + b1);
            }
        }
    }
}

// ---------------- SpMM over fp16 features (warp/row, uint4 gathers) + tanh --

// Layer 1: 500 half features, pitch 512 halves (= 64 uint4); out HALF pitch 512
__global__ __launch_bounds__(256) void spmm1_tanh_h_kernel(int n)
{
    const uint4* Hh = (const uint4*)g_H;       // 8 halves per uint4
    __half2* Out2 = (__half2*)g_A;

    int gw = (blockIdx.x * blockDim.x + threadIdx.x) >> 5;
    if (gw >= n) return;
    int lane = threadIdx.x & 31;

    float2 acc[2][4];
    #pragma unroll
    for (int q = 0; q < 2; ++q)
        #pragma unroll
        for (int p = 0; p < 4; ++p) acc[q][p] = make_float2(0.f, 0.f);

    int s = g_rowptr[gw], e = g_rowptr[gw + 1];
    for (int j = s; j < e; ++j) {
        int   c  = __ldg(&g_colidx[j]);
        float wj = __ldg(&g_wnorm[j]);
        const uint4* base = Hh + (size_t)c * 64;
        #pragma unroll
        for (int q = 0; q < 2; ++q) {
            int idx = lane + 32 * q;
            if (idx < 63) {                    // 63 uint4 cover 504 >= 500 halves
                uint4 v = base[idx];
                #pragma unroll
                for (int p = 0; p < 4; ++p) {
                    float2 f = __half22float2(*(const __half2*)((&v.x) + p));
                    acc[q][p].x += wj * f.x;
                    acc[q][p].y += wj * f.y;
                }
            }
        }
    }
    #pragma unroll
    for (int q = 0; q < 2; ++q) {
        int idx = lane + 32 * q;
        if (idx < 63) {
            #pragma unroll
            for (int p = 0; p < 4; ++p) {
                int col = 8 * idx + 2 * p;
                if (col < 500) {
                    Out2[(size_t)gw * 256 + (col >> 1)] =
                        __floats2half2_rn(tanhf(acc[q][p].x), tanhf(acc[q][p].y));
                }
            }
        }
    }
}

// Layer 2: 100 half features, pitch 128 halves (= 64 half2); out fp32 pitch 128
__global__ __launch_bounds__(256) void spmm2_tanh_h_kernel(int n)
{
    const __half2* Hh = (const __half2*)g_H;
    float* Out = g_A;

    int gw = (blockIdx.x * blockDim.x + threadIdx.x) >> 5;
    if (gw >= n) return;
    int lane = threadIdx.x & 31;

    float2 acc[2];
    acc[0] = make_float2(0.f, 0.f);
    acc[1] = make_float2(0.f, 0.f);

    int s = g_rowptr[gw], e = g_rowptr[gw + 1];
    for (int j = s; j < e; ++j) {
        int   c  = __ldg(&g_colidx[j]);
        float wj = __ldg(&g_wnorm[j]);
        const __half2* base = Hh + (size_t)c * 64;
        #pragma unroll
        for (int q = 0; q < 2; ++q) {
            int idx = lane + 32 * q;
            if (idx < 50) {                    // 50 half2 = 100 halves
                float2 f = __half22float2(base[idx]);
                acc[q].x += wj * f.x;
                acc[q].y += wj * f.y;
            }
        }
    }
    #pragma unroll
    for (int q = 0; q < 2; ++q) {
        int idx = lane + 32 * q;
        if (idx < 50) {
            float2 t = make_float2(tanhf(acc[q].x), tanhf(acc[q].y));
            *(float2*)&Out[(size_t)gw * 128 + 2 * idx] = t;
        }
    }
}

// ---------------- layer 3: tiny GEMM + fused SpMM/tanh/softmax --------------

__global__ __launch_bounds__(256) void gemm3_kernel(
    const float* __restrict__ W3, const float* __restrict__ b3, int n)
{
    __shared__ float Ws[H2D * NCLS];
    __shared__ float bs[NCLS];
    for (int i = threadIdx.x; i < H2D * NCLS; i += 256) Ws[i] = W3[i];
    if (threadIdx.x < NCLS) bs[threadIdx.x] = b3[threadIdx.x];
    __syncthreads();

    int row = blockIdx.x * blockDim.x + threadIdx.x;
    if (row >= n) return;
    float acc[NCLS];
    #pragma unroll
    for (int j = 0; j < NCLS; j++) acc[j] = bs[j];
    const float* a = g_A + (size_t)row * 128;
    for (int k = 0; k < H2D; ++k) {
        float av = a[k];
        #pragma unroll
        for (int j = 0; j < NCLS; j++) acc[j] += av * Ws[k * NCLS + j];
    }
    float* o = g_H + (size_t)row * NCLS;
    #pragma unroll
    for (int j = 0; j < NCLS; j++) o[j] = acc[j];
}

__global__ __launch_bounds__(256) void spmm3_softmax_kernel(float* __restrict__ out, int n)
{
    int row = blockIdx.x * blockDim.x + threadIdx.x;
    if (row >= n) return;
    float acc[NCLS];
    #pragma unroll
    for (int j = 0; j < NCLS; j++) acc[j] = 0.f;

    int s = g_rowptr[row], e = g_rowptr[row + 1];
    for (int j = s; j < e; ++j) {
        int   c  = g_colidx[j];
        float wj = g_wnorm[j];
        const float4* b = (const float4*)(g_H + (size_t)c * NCLS);
        #pragma unroll
        for (int q = 0; q < 4; ++q) {
            float4 v = b[q];
            acc[4 * q + 0] += wj * v.x; acc[4 * q + 1] += wj * v.y;
            acc[4 * q + 2] += wj * v.z; acc[4 * q + 3] += wj * v.w;
        }
    }
    float mx = -1e30f;
    #pragma unroll
    for (int j = 0; j < NCLS; j++) { acc[j] = tanhf(acc[j]); mx = fmaxf(mx, acc[j]); }
    float sum = 0.f;
    #pragma unroll
    for (int j = 0; j < NCLS; j++) { acc[j] = expf(acc[j] - mx); sum += acc[j]; }
    float inv = 1.f / sum;
    float* o = out + (size_t)row * NCLS;
    #pragma unroll
    for (int j = 0; j < NCLS; j++) o[j] = acc[j] * inv;
}

// ---------------- launch ----------------

extern "C" void kernel_launch(void* const* d_in, const int* in_sizes, int n_in,
                              void* d_out, int out_size)
{
    const float* x  = (const float*)d_in[0];
    const void*  ei = d_in[1];
    const float* W1 = (const float*)d_in[2];
    const float* b1 = (const float*)d_in[3];
    const float* W2 = (const float*)d_in[4];
    const float* b2 = (const float*)d_in[5];
    const float* W3 = (const float*)d_in[6];
    const float* b3 = (const float*)d_in[7];
    float* out = (float*)d_out;

    int n = in_sizes[0] / F_IN;   // 50000
    int E = in_sizes[1] / 2;      // 800000

    // fork a side stream: CSR build runs concurrently with GEMM1
    cudaStream_t s2;
    cudaStreamCreateWithFlags(&s2, cudaStreamNonBlocking);
    cudaEvent_t evFork, evJoin;
    cudaEventCreateWithFlags(&evFork, cudaEventDisableTiming);
    cudaEventCreateWithFlags(&evJoin, cudaEventDisableTiming);

    cudaEventRecord(evFork, 0);
    cudaStreamWaitEvent(s2, evFork, 0);

    // --- CSR build (stream s2) ---
    detect_init_kernel<<<1 + (n + 255) / 256, 256, 0, s2>>>((const long long*)ei, n);
    hist_kernel<<<(E + 255) / 256, 256, 0, s2>>>(ei, E);
    dinv_kernel<<<(n + 255) / 256, 256, 0, s2>>>(n);
    scan_kernel<<<1, 1024, 0, s2>>>(n);
    fill_kernel<<<(E + n + 255) / 256, 256, 0, s2>>>(ei, E, n);
    cudaEventRecord(evJoin, s2);

    // --- layer 1 GEMM (main stream, concurrent with CSR) ---
    {
        dim3 g((H1D + BN - 1) / BN, (n + BM - 1) / BM);
        gemm_mma_kernel<<<g, 256>>>(x, 2, F_IN, W1, H1D, b1, 256, n, H1D, F_IN);
    }

    // join: SpMM1 needs both CSR and GEMM1
    cudaStreamWaitEvent(0, evJoin, 0);
    spmm1_tanh_h_kernel<<<(n * 32 + 255) / 256, 256>>>(n);

    // --- layer 2: FP16 GEMM [N,500(half)]x[500,100] -> g_H half (pitch 128h), SpMM+tanh -> g_A fp32
    {
        dim3 g((H2D + BN - 1) / BN, (n + BM - 1) / BM);
        gemm_mma_kernel<<<g, 256>>>(nullptr, 1, 512, W2, H2D, b2, 64, n, H2D, H1D);
    }
    spmm2_tanh_h_kernel<<<(n * 32 + 255) / 256, 256>>>(n);

    // --- layer 3: tiny GEMM -> g_H fp32 (pitch 16), fused SpMM+tanh+softmax -> out
    gemm3_kernel<<<(n + 255) / 256, 256>>>(W3, b3, n);
    spmm3_softmax_kernel<<<(n + 255) / 256, 256>>>(out, n);

    cudaEventDestroy(evFork);
    cudaEventDestroy(evJoin);
    cudaStreamDestroy(s2);
}

// round 8
// speedup vs baseline: 2.2469x; 1.1245x over previous
#include <cuda_runtime.h>
#include <cuda_fp16.h>
#include <math.h>
#include <stdint.h>

#define N_NODES 50000
#define F_IN    512
#define H1D     500
#define H2D     100
#define NCLS    16
#define NB_SCAN 196     // ceil(50000/256)

// ---------------- device scratch (no allocations allowed) ----------------
__device__ __align__(16) float g_H[(size_t)N_NODES * 512];   // half for L1/L2 GEMM out, fp32 for gemm3
__device__ __align__(16) float g_A[(size_t)N_NODES * 512];   // half for spmm1 out, fp32 for spmm2 out
__device__ int   g_deg[N_NODES];
__device__ float g_dinv[N_NODES];
__device__ int   g_rowptr[N_NODES + 1];
__device__ int   g_cursor[N_NODES];
__device__ int   g_colidx[800000 + N_NODES];
__device__ float g_wnorm[800000 + N_NODES];
__device__ int   g_part[256];
__device__ int   g_poff[256];
__device__ int   g_is64;

// ---------------- graph preprocessing ----------------

// block 0: dtype detect; blocks 1..: deg init (self loop)
__global__ void detect_init_kernel(const long long* __restrict__ ei, int n) {
    if (blockIdx.x == 0) {
        __shared__ int bad;
        if (threadIdx.x == 0) bad = 0;
        __syncthreads();
        #pragma unroll
        for (int i = 0; i < 4; ++i) {
            long long v = ei[threadIdx.x * 4 + i];
            if (v < 0 || v >= (long long)N_NODES) bad = 1;
        }
        __syncthreads();
        if (threadIdx.x == 0) g_is64 = bad ? 0 : 1;
    } else {
        int i = (blockIdx.x - 1) * blockDim.x + threadIdx.x;
        if (i < n) g_deg[i] = 1;
    }
}

__global__ void hist_kernel(const void* __restrict__ ei, int E) {
    int e = blockIdx.x * blockDim.x + threadIdx.x;
    if (e >= E) return;
    int r = g_is64 ? (int)((const long long*)ei)[e] : ((const int*)ei)[e];
    atomicAdd(&g_deg[r], 1);
}

// phase 1: per-block sum of 256 degrees -> g_part[block]
__global__ __launch_bounds__(256) void scan_p1_kernel(int n) {
    __shared__ int sm[256];
    int t = threadIdx.x;
    int i = blockIdx.x * 256 + t;
    sm[t] = (i < n) ? g_deg[i] : 0;
    __syncthreads();
    #pragma unroll
    for (int off = 128; off > 0; off >>= 1) {
        if (t < off) sm[t] += sm[t + off];
        __syncthreads();
    }
    if (t == 0) g_part[blockIdx.x] = sm[0];
}

// phase 2: exclusive scan of NB_SCAN partials (single tiny block)
__global__ __launch_bounds__(256) void scan_p2_kernel() {
    __shared__ int sm[256];
    int t = threadIdx.x;
    int v = (t < NB_SCAN) ? g_part[t] : 0;
    sm[t] = v;
    __syncthreads();
    #pragma unroll
    for (int off = 1; off < 256; off <<= 1) {
        int u = (t >= off) ? sm[t - off] : 0;
        __syncthreads();
        sm[t] += u;
        __syncthreads();
    }
    if (t < NB_SCAN) g_poff[t] = sm[t] - v;    // exclusive
}

// phase 3: per-block inclusive scan + global offset -> rowptr/cursor, plus dinv
__global__ __launch_bounds__(256) void scan_p3_kernel(int n) {
    __shared__ int sm[256];
    int t = threadIdx.x;
    int i = blockIdx.x * 256 + t;
    int d = (i < n) ? g_deg[i] : 0;
    sm[t] = d;
    __syncthreads();
    #pragma unroll
    for (int off = 1; off < 256; off <<= 1) {
        int u = (t >= off) ? sm[t - off] : 0;
        __syncthreads();
        sm[t] += u;
        __syncthreads();
    }
    int base = g_poff[blockIdx.x];
    if (i < n) {
        int excl = base + sm[t] - d;
        g_rowptr[i] = excl;
        g_cursor[i] = excl;
        g_dinv[i]   = rsqrtf((float)d);        // d >= 1 always
        if (i == n - 1) g_rowptr[n] = excl + d;
    }
}

__global__ void fill_kernel(const void* __restrict__ ei, int E, int n) {
    int t = blockIdx.x * blockDim.x + threadIdx.x;
    if (t < E) {
        int r, c;
        if (g_is64) {
            r = (int)((const long long*)ei)[t];
            c = (int)((const long long*)ei)[E + t];
        } else {
            r = ((const int*)ei)[t];
            c = ((const int*)ei)[E + t];
        }
        int pos = atomicAdd(&g_cursor[r], 1);
        g_colidx[pos] = c;
        g_wnorm[pos]  = g_dinv[r] * g_dinv[c];
    } else if (t < E + n) {
        int i = t - E;
        int pos = atomicAdd(&g_cursor[i], 1);
        g_colidx[pos] = i;
        g_wnorm[pos]  = g_dinv[i] * g_dinv[i];
    }
}

// ---------------- FP16 mma.sync GEMM (m16n8k16), fp16 output ----------

#define BM  128
#define BN  128
#define BK  16
#define ASTR2 12    // As row stride in half2: frag addr 12g+tig distinct mod 32
#define BSTR2 136   // Bs row stride in half2: frag addr 8*tig+g distinct mod 32

// C[m][n] = sum_k A[m][k]*B[k][n] + bias[n]; C -> g_H as __half2, pitch ldc2 half2
// a_id: 1 => A = g_A as half (lda in halves); 2 => A = Aext fp32 (lda in floats)
__global__ __launch_bounds__(256, 1) void gemm_mma_kernel(
    const float* __restrict__ Aext, int a_id, int lda,
    const float* __restrict__ B, int ldb,
    const float* __restrict__ bias,
    int ldc2, int M, int Nn, int K)
{
    __shared__ __half2 As2[2][BM][ASTR2];   // cols 0..7 used (16 halves)
    __shared__ __half2 Bs2[2][BK / 2][BSTR2];
    __shared__ float sbias[BN];

    const float*  Af = (a_id == 2) ? Aext : nullptr;
    const __half* Ah = (a_id == 1) ? (const __half*)g_A : nullptr;
    __half2* C2 = (__half2*)g_H;

    int tid = threadIdx.x, wid = tid >> 5, lane = tid & 31;
    int g = lane >> 2, tig = lane & 3;
    int wr = wid & 3, wc = wid >> 2;            // 4x2 warp grid
    int m0 = blockIdx.y * BM, n0 = blockIdx.x * BN;

    if (tid < BN) {
        sbias[tid] = (n0 + tid < Nn) ? bias[n0 + tid] : 0.f;
    }

    float acc[2][8][4];
    #pragma unroll
    for (int i = 0; i < 2; i++)
        #pragma unroll
        for (int j = 0; j < 8; j++)
            #pragma unroll
            for (int q = 0; q < 4; q++) acc[i][j][q] = 0.f;

    int nIter = (K + BK - 1) >> 4;

    // preload chunk 0
    {
        int k0 = 0;
        #pragma unroll
        for (int p = 0; p < 2; ++p) {
            int f = p * 256 + tid;
            int r = f >> 2, c4 = f & 3;
            int gm = m0 + r;
            float v[4] = {0.f, 0.f, 0.f, 0.f};
            if (gm < M) {
                if (a_id == 2) {
                    if (k0 + 16 <= K) {
                        float4 t = *(const float4*)&Af[(size_t)gm * lda + k0 + c4 * 4];
                        v[0] = t.x; v[1] = t.y; v[2] = t.z; v[3] = t.w;
                    } else {
                        #pragma unroll
                        for (int e = 0; e < 4; ++e) {
                            int gk = k0 + c4 * 4 + e;
                            if (gk < K) v[e] = Af[(size_t)gm * lda + gk];
                        }
                    }
                } else {
                    if (k0 + 16 <= K) {
                        uint2 t = *(const uint2*)&Ah[(size_t)gm * lda + k0 + c4 * 4];
                        __half2 h0 = *(__half2*)&t.x, h1 = *(__half2*)&t.y;
                        float2 f0 = __half22float2(h0), f1 = __half22float2(h1);
                        v[0] = f0.x; v[1] = f0.y; v[2] = f1.x; v[3] = f1.y;
                    } else {
                        #pragma unroll
                        for (int e = 0; e < 4; ++e) {
                            int gk = k0 + c4 * 4 + e;
                            if (gk < K) v[e] = __half2float(Ah[(size_t)gm * lda + gk]);
                        }
                    }
                }
            }
            As2[0][r][2 * c4]     = __floats2half2_rn(v[0], v[1]);
            As2[0][r][2 * c4 + 1] = __floats2half2_rn(v[2], v[3]);
        }
        #pragma unroll
        for (int p = 0; p < 4; ++p) {
            int e = p * 256 + tid;
            int r = e >> 7, c = e & 127;
            int gk = k0 + 2 * r, gn = n0 + c;
            float v0 = (gk < K && gn < Nn) ? B[(size_t)gk * ldb + gn] : 0.f;
            float v1 = (gk + 1 < K && gn < Nn) ? B[(size_t)(gk + 1) * ldb + gn] : 0.f;
            Bs2[0][r][c] = __floats2half2_rn(v0, v1);
        }
    }
    __syncthreads();

    int buf = 0;
    for (int it = 0; it < nIter; ++it) {
        bool hasNext = (it + 1) < nIter;
        int k1 = (it + 1) << 4;
        float ra[2][4];
        float rb[4][2];
        if (hasNext) {
            #pragma unroll
            for (int p = 0; p < 2; ++p) {
                int f = p * 256 + tid;
                int r = f >> 2, c4 = f & 3;
                int gm = m0 + r;
                ra[p][0] = ra[p][1] = ra[p][2] = ra[p][3] = 0.f;
                if (gm < M) {
                    if (a_id == 2) {
                        if (k1 + 16 <= K) {
                            float4 t = *(const float4*)&Af[(size_t)gm * lda + k1 + c4 * 4];
                            ra[p][0] = t.x; ra[p][1] = t.y; ra[p][2] = t.z; ra[p][3] = t.w;
                        } else {
                            #pragma unroll
                            for (int e = 0; e < 4; ++e) {
                                int gk = k1 + c4 * 4 + e;
                                if (gk < K) ra[p][e] = Af[(size_t)gm * lda + gk];
                            }
                        }
                    } else {
                        if (k1 + 16 <= K) {
                            uint2 t = *(const uint2*)&Ah[(size_t)gm * lda + k1 + c4 * 4];
                            __half2 h0 = *(__half2*)&t.x, h1 = *(__half2*)&t.y;
                            float2 f0 = __half22float2(h0), f1 = __half22float2(h1);
                            ra[p][0] = f0.x; ra[p][1] = f0.y; ra[p][2] = f1.x; ra[p][3] = f1.y;
                        } else {
                            #pragma unroll
                            for (int e = 0; e < 4; ++e) {
                                int gk = k1 + c4 * 4 + e;
                                if (gk < K) ra[p][e] = __half2float(Ah[(size_t)gm * lda + gk]);
                            }
                        }
                    }
                }
            }
            #pragma unroll
            for (int p = 0; p < 4; ++p) {
                int e = p * 256 + tid;
                int r = e >> 7, c = e & 127;
                int gk = k1 + 2 * r, gn = n0 + c;
                rb[p][0] = (gk < K && gn < Nn) ? B[(size_t)gk * ldb + gn] : 0.f;
                rb[p][1] = (gk + 1 < K && gn < Nn) ? B[(size_t)(gk + 1) * ldb + gn] : 0.f;
            }
        }

        // ---- one m16n8k16 MMA sweep covers the whole BK=16 chunk ----
        {
            uint32_t af[2][4];
            #pragma unroll
            for (int i = 0; i < 2; ++i) {
                int rA = wr * 32 + i * 16;
                af[i][0] = *(const uint32_t*)&As2[buf][rA + g    ][tig    ];
                af[i][1] = *(const uint32_t*)&As2[buf][rA + g + 8][tig    ];
                af[i][2] = *(const uint32_t*)&As2[buf][rA + g    ][tig + 4];
                af[i][3] = *(const uint32_t*)&As2[buf][rA + g + 8][tig + 4];
            }
            uint32_t bf[8][2];
            #pragma unroll
            for (int j = 0; j < 8; ++j) {
                int cB = wc * 64 + j * 8 + g;
                bf[j][0] = *(const uint32_t*)&Bs2[buf][tig    ][cB];
                bf[j][1] = *(const uint32_t*)&Bs2[buf][tig + 4][cB];
            }
            #pragma unroll
            for (int i = 0; i < 2; ++i)
                #pragma unroll
                for (int j = 0; j < 8; ++j) {
                    asm volatile(
                        "mma.sync.aligned.m16n8k16.row.col.f32.f16.f16.f32 "
                        "{%0,%1,%2,%3}, {%4,%5,%6,%7}, {%8,%9}, {%0,%1,%2,%3};"
                        : "+f"(acc[i][j][0]), "+f"(acc[i][j][1]),
                          "+f"(acc[i][j][2]), "+f"(acc[i][j][3])
                        : "r"(af[i][0]), "r"(af[i][1]), "r"(af[i][2]), "r"(af[i][3]),
                          "r"(bf[j][0]), "r"(bf[j][1]));
                }
        }

        if (hasNext) {
            int nb = buf ^ 1;
            #pragma unroll
            for (int p = 0; p < 2; ++p) {
                int f = p * 256 + tid;
                int r = f >> 2, c4 = f & 3;
                As2[nb][r][2 * c4]     = __floats2half2_rn(ra[p][0], ra[p][1]);
                As2[nb][r][2 * c4 + 1] = __floats2half2_rn(ra[p][2], ra[p][3]);
            }
            #pragma unroll
            for (int p = 0; p < 4; ++p) {
                int e = p * 256 + tid;
                int r = e >> 7, c = e & 127;
                Bs2[nb][r][c] = __floats2half2_rn(rb[p][0], rb[p][1]);
            }
        }
        __syncthreads();
        buf ^= 1;
    }

    // ---- epilogue: bias add, half2 stores ----
    #pragma unroll
    for (int i = 0; i < 2; ++i) {
        int r0 = m0 + wr * 32 + i * 16 + g;
        int r1 = r0 + 8;
        #pragma unroll
        for (int j = 0; j < 8; ++j) {
            int nn = n0 + wc * 64 + j * 8 + 2 * tig;   // always even
            if (nn < Nn) {
                float b0 = sbias[wc * 64 + j * 8 + 2 * tig];
                float b1 = sbias[wc * 64 + j * 8 + 2 * tig + 1];
                if (r0 < M)
                    C2[(size_t)r0 * ldc2 + (nn >> 1)] =
                        __floats2half2_rn(acc[i][j][0] + b0, acc[i][j][1] + b1);
                if (r1 < M)
                    C2[(size_t)r1 * ldc2 + (nn >> 1)] =
                        __floats2half2_rn(acc[i][j][2] + b0, acc[i][j][3] + b1);
            }
        }
    }
}

// ---------------- SpMM over fp16 features (warp/row, uint4 gathers) + tanh --

// Layer 1: 500 half features, pitch 512 halves (= 64 uint4); out HALF pitch 512
__global__ __launch_bounds__(256) void spmm1_tanh_h_kernel(int n)
{
    const uint4* Hh = (const uint4*)g_H;       // 8 halves per uint4
    __half2* Out2 = (__half2*)g_A;

    int gw = (blockIdx.x * blockDim.x + threadIdx.x) >> 5;
    if (gw >= n) return;
    int lane = threadIdx.x & 31;

    float2 acc[2][4];
    #pragma unroll
    for (int q = 0; q < 2; ++q)
        #pragma unroll
        for (int p = 0; p < 4; ++p) acc[q][p] = make_float2(0.f, 0.f);

    int s = g_rowptr[gw], e = g_rowptr[gw + 1];
    for (int j = s; j < e; ++j) {
        int   c  = __ldg(&g_colidx[j]);
        float wj = __ldg(&g_wnorm[j]);
        const uint4* base = Hh + (size_t)c * 64;
        #pragma unroll
        for (int q = 0; q < 2; ++q) {
            int idx = lane + 32 * q;
            if (idx < 63) {                    // 63 uint4 cover 504 >= 500 halves
                uint4 v = base[idx];
                #pragma unroll
                for (int p = 0; p < 4; ++p) {
                    float2 f = __half22float2(*(const __half2*)((&v.x) + p));
                    acc[q][p].x += wj * f.x;
                    acc[q][p].y += wj * f.y;
                }
            }
        }
    }
    #pragma unroll
    for (int q = 0; q < 2; ++q) {
        int idx = lane + 32 * q;
        if (idx < 63) {
            #pragma unroll
            for (int p = 0; p < 4; ++p) {
                int col = 8 * idx + 2 * p;
                if (col < 500) {
                    Out2[(size_t)gw * 256 + (col >> 1)] =
                        __floats2half2_rn(tanhf(acc[q][p].x), tanhf(acc[q][p].y));
                }
            }
        }
    }
}

// Layer 2: 100 half features, pitch 128 halves (= 64 half2); out fp32 pitch 128
__global__ __launch_bounds__(256) void spmm2_tanh_h_kernel(int n)
{
    const __half2* Hh = (const __half2*)g_H;
    float* Out = g_A;

    int gw = (blockIdx.x * blockDim.x + threadIdx.x) >> 5;
    if (gw >= n) return;
    int lane = threadIdx.x & 31;

    float2 acc[2];
    acc[0] = make_float2(0.f, 0.f);
    acc[1] = make_float2(0.f, 0.f);

    int s = g_rowptr[gw], e = g_rowptr[gw + 1];
    for (int j = s; j < e; ++j) {
        int   c  = __ldg(&g_colidx[j]);
        float wj = __ldg(&g_wnorm[j]);
        const __half2* base = Hh + (size_t)c * 64;
        #pragma unroll
        for (int q = 0; q < 2; ++q) {
            int idx = lane + 32 * q;
            if (idx < 50) {                    // 50 half2 = 100 halves
                float2 f = __half22float2(base[idx]);
                acc[q].x += wj * f.x;
                acc[q].y += wj * f.y;
            }
        }
    }
    #pragma unroll
    for (int q = 0; q < 2; ++q) {
        int idx = lane + 32 * q;
        if (idx < 50) {
            float2 t = make_float2(tanhf(acc[q].x), tanhf(acc[q].y));
            *(float2*)&Out[(size_t)gw * 128 + 2 * idx] = t;
        }
    }
}

// ---------------- layer 3: tiny GEMM + fused SpMM/tanh/softmax --------------

__global__ __launch_bounds__(256) void gemm3_kernel(
    const float* __restrict__ W3, const float* __restrict__ b3, int n)
{
    __shared__ float Ws[H2D * NCLS];
    __shared__ float bs[NCLS];
    for (int i = threadIdx.x; i < H2D * NCLS; i += 256) Ws[i] = W3[i];
    if (threadIdx.x < NCLS) bs[threadIdx.x] = b3[threadIdx.x];
    __syncthreads();

    int row = blockIdx.x * blockDim.x + threadIdx.x;
    if (row >= n) return;
    float acc[NCLS];
    #pragma unroll
    for (int j = 0; j < NCLS; j++) acc[j] = bs[j];
    const float* a = g_A + (size_t)row * 128;
    for (int k = 0; k < H2D; ++k) {
        float av = a[k];
        #pragma unroll
        for (int j = 0; j < NCLS; j++) acc[j] += av * Ws[k * NCLS + j];
    }
    float* o = g_H + (size_t)row * NCLS;
    #pragma unroll
    for (int j = 0; j < NCLS; j++) o[j] = acc[j];
}

__global__ __launch_bounds__(256) void spmm3_softmax_kernel(float* __restrict__ out, int n)
{
    int row = blockIdx.x * blockDim.x + threadIdx.x;
    if (row >= n) return;
    float acc[NCLS];
    #pragma unroll
    for (int j = 0; j < NCLS; j++) acc[j] = 0.f;

    int s = g_rowptr[row], e = g_rowptr[row + 1];
    for (int j = s; j < e; ++j) {
        int   c  = g_colidx[j];
        float wj = g_wnorm[j];
        const float4* b = (const float4*)(g_H + (size_t)c * NCLS);
        #pragma unroll
        for (int q = 0; q < 4; ++q) {
            float4 v = b[q];
            acc[4 * q + 0] += wj * v.x; acc[4 * q + 1] += wj * v.y;
            acc[4 * q + 2] += wj * v.z; acc[4 * q + 3] += wj * v.w;
        }
    }
    float mx = -1e30f;
    #pragma unroll
    for (int j = 0; j < NCLS; j++) { acc[j] = tanhf(acc[j]); mx = fmaxf(mx, acc[j]); }
    float sum = 0.f;
    #pragma unroll
    for (int j = 0; j < NCLS; j++) { acc[j] = expf(acc[j] - mx); sum += acc[j]; }
    float inv = 1.f / sum;
    float* o = out + (size_t)row * NCLS;
    #pragma unroll
    for (int j = 0; j < NCLS; j++) o[j] = acc[j] * inv;
}

// ---------------- launch ----------------

extern "C" void kernel_launch(void* const* d_in, const int* in_sizes, int n_in,
                              void* d_out, int out_size)
{
    const float* x  = (const float*)d_in[0];
    const void*  ei = d_in[1];
    const float* W1 = (const float*)d_in[2];
    const float* b1 = (const float*)d_in[3];
    const float* W2 = (const float*)d_in[4];
    const float* b2 = (const float*)d_in[5];
    const float* W3 = (const float*)d_in[6];
    const float* b3 = (const float*)d_in[7];
    float* out = (float*)d_out;

    int n = in_sizes[0] / F_IN;   // 50000
    int E = in_sizes[1] / 2;      // 800000

    // fork a side stream: CSR build runs concurrently with GEMM1
    cudaStream_t s2;
    cudaStreamCreateWithFlags(&s2, cudaStreamNonBlocking);
    cudaEvent_t evFork, evJoin;
    cudaEventCreateWithFlags(&evFork, cudaEventDisableTiming);
    cudaEventCreateWithFlags(&evJoin, cudaEventDisableTiming);

    cudaEventRecord(evFork, 0);
    cudaStreamWaitEvent(s2, evFork, 0);

    // --- CSR build (stream s2) ---
    detect_init_kernel<<<1 + (n + 255) / 256, 256, 0, s2>>>((const long long*)ei, n);
    hist_kernel<<<(E + 255) / 256, 256, 0, s2>>>(ei, E);
    scan_p1_kernel<<<NB_SCAN, 256, 0, s2>>>(n);
    scan_p2_kernel<<<1, 256, 0, s2>>>();
    scan_p3_kernel<<<NB_SCAN, 256, 0, s2>>>(n);
    fill_kernel<<<(E + n + 255) / 256, 256, 0, s2>>>(ei, E, n);
    cudaEventRecord(evJoin, s2);

    // --- layer 1 GEMM (main stream, concurrent with CSR) ---
    {
        dim3 g((H1D + BN - 1) / BN, (n + BM - 1) / BM);
        gemm_mma_kernel<<<g, 256>>>(x, 2, F_IN, W1, H1D, b1, 256, n, H1D, F_IN);
    }

    // join: SpMM1 needs both CSR and GEMM1
    cudaStreamWaitEvent(0, evJoin, 0);
    spmm1_tanh_h_kernel<<<(n * 32 + 255) / 256, 256>>>(n);

    // --- layer 2: FP16 GEMM [N,500(half)]x[500,100] -> g_H half (pitch 128h), SpMM+tanh -> g_A fp32
    {
        dim3 g((H2D + BN - 1) / BN, (n + BM - 1) / BM);
        gemm_mma_kernel<<<g, 256>>>(nullptr, 1, 512, W2, H2D, b2, 64, n, H2D, H1D);
    }
    spmm2_tanh_h_kernel<<<(n * 32 + 255) / 256, 256>>>(n);

    // --- layer 3: tiny GEMM -> g_H fp32 (pitch 16), fused SpMM+tanh+softmax -> out
    gemm3_kernel<<<(n + 255) / 256, 256>>>(W3, b3, n);
    spmm3_softmax_kernel<<<(n + 255) / 256, 256>>>(out, n);

    cudaEventDestroy(evFork);
    cudaEventDestroy(evJoin);
    cudaStreamDestroy(s2);
}

// round 9
// speedup vs baseline: 2.2535x; 1.0029x over previous
#include <cuda_runtime.h>
#include <cuda_fp16.h>
#include <math.h>
#include <stdint.h>

#define N_NODES 50000
#define F_IN    512
#define H1D     500
#define H2D     100
#define NCLS    16
#define NB_SCAN 196     // ceil(50000/256)

// ---------------- device scratch (no allocations allowed) ----------------
__device__ __align__(16) float g_H[(size_t)N_NODES * 512];   // half: GEMM1/GEMM2 out
__device__ __align__(16) float g_A[(size_t)N_NODES * 512];   // half: spmm1 out, then h3 out
__device__ int   g_deg[N_NODES];
__device__ float g_dinv[N_NODES];
__device__ int   g_rowptr[N_NODES + 1];
__device__ int   g_cursor[N_NODES];
__device__ int   g_colidx[800000 + N_NODES];
__device__ float g_wnorm[800000 + N_NODES];
__device__ int   g_part[256];
__device__ int   g_poff[256];
__device__ int   g_is64;

// ---------------- graph preprocessing ----------------

__global__ void detect_init_kernel(const long long* __restrict__ ei, int n) {
    if (blockIdx.x == 0) {
        __shared__ int bad;
        if (threadIdx.x == 0) bad = 0;
        __syncthreads();
        #pragma unroll
        for (int i = 0; i < 4; ++i) {
            long long v = ei[threadIdx.x * 4 + i];
            if (v < 0 || v >= (long long)N_NODES) bad = 1;
        }
        __syncthreads();
        if (threadIdx.x == 0) g_is64 = bad ? 0 : 1;
    } else {
        int i = (blockIdx.x - 1) * blockDim.x + threadIdx.x;
        if (i < n) g_deg[i] = 1;
    }
}

__global__ void hist_kernel(const void* __restrict__ ei, int E) {
    int e = blockIdx.x * blockDim.x + threadIdx.x;
    if (e >= E) return;
    int r = g_is64 ? (int)((const long long*)ei)[e] : ((const int*)ei)[e];
    atomicAdd(&g_deg[r], 1);
}

__global__ __launch_bounds__(256) void scan_p1_kernel(int n) {
    __shared__ int sm[256];
    int t = threadIdx.x;
    int i = blockIdx.x * 256 + t;
    sm[t] = (i < n) ? g_deg[i] : 0;
    __syncthreads();
    #pragma unroll
    for (int off = 128; off > 0; off >>= 1) {
        if (t < off) sm[t] += sm[t + off];
        __syncthreads();
    }
    if (t == 0) g_part[blockIdx.x] = sm[0];
}

__global__ __launch_bounds__(256) void scan_p2_kernel() {
    __shared__ int sm[256];
    int t = threadIdx.x;
    int v = (t < NB_SCAN) ? g_part[t] : 0;
    sm[t] = v;
    __syncthreads();
    #pragma unroll
    for (int off = 1; off < 256; off <<= 1) {
        int u = (t >= off) ? sm[t - off] : 0;
        __syncthreads();
        sm[t] += u;
        __syncthreads();
    }
    if (t < NB_SCAN) g_poff[t] = sm[t] - v;    // exclusive
}

__global__ __launch_bounds__(256) void scan_p3_kernel(int n) {
    __shared__ int sm[256];
    int t = threadIdx.x;
    int i = blockIdx.x * 256 + t;
    int d = (i < n) ? g_deg[i] : 0;
    sm[t] = d;
    __syncthreads();
    #pragma unroll
    for (int off = 1; off < 256; off <<= 1) {
        int u = (t >= off) ? sm[t - off] : 0;
        __syncthreads();
        sm[t] += u;
        __syncthreads();
    }
    int base = g_poff[blockIdx.x];
    if (i < n) {
        int excl = base + sm[t] - d;
        g_rowptr[i] = excl;
        g_cursor[i] = excl;
        g_dinv[i]   = rsqrtf((float)d);
        if (i == n - 1) g_rowptr[n] = excl + d;
    }
}

__global__ void fill_kernel(const void* __restrict__ ei, int E, int n) {
    int t = blockIdx.x * blockDim.x + threadIdx.x;
    if (t < E) {
        int r, c;
        if (g_is64) {
            r = (int)((const long long*)ei)[t];
            c = (int)((const long long*)ei)[E + t];
        } else {
            r = ((const int*)ei)[t];
            c = ((const int*)ei)[E + t];
        }
        int pos = atomicAdd(&g_cursor[r], 1);
        g_colidx[pos] = c;
        g_wnorm[pos]  = g_dinv[r] * g_dinv[c];
    } else if (t < E + n) {
        int i = t - E;
        int pos = atomicAdd(&g_cursor[i], 1);
        g_colidx[pos] = i;
        g_wnorm[pos]  = g_dinv[i] * g_dinv[i];
    }
}

// ---------------- FP16 mma.sync GEMM (m16n8k16), fp16 output ----------

#define BM  128
#define BN  128
#define BK  16
#define ASTR2 12
#define BSTR2 136

__global__ __launch_bounds__(256, 1) void gemm_mma_kernel(
    const float* __restrict__ Aext, int a_id, int lda,
    const float* __restrict__ B, int ldb,
    const float* __restrict__ bias,
    int ldc2, int M, int Nn, int K)
{
    __shared__ __half2 As2[2][BM][ASTR2];
    __shared__ __half2 Bs2[2][BK / 2][BSTR2];
    __shared__ float sbias[BN];

    const float*  Af = (a_id == 2) ? Aext : nullptr;
    const __half* Ah = (a_id == 1) ? (const __half*)g_A : nullptr;
    __half2* C2 = (__half2*)g_H;

    int tid = threadIdx.x, wid = tid >> 5, lane = tid & 31;
    int g = lane >> 2, tig = lane & 3;
    int wr = wid & 3, wc = wid >> 2;
    int m0 = blockIdx.y * BM, n0 = blockIdx.x * BN;

    if (tid < BN) {
        sbias[tid] = (n0 + tid < Nn) ? bias[n0 + tid] : 0.f;
    }

    float acc[2][8][4];
    #pragma unroll
    for (int i = 0; i < 2; i++)
        #pragma unroll
        for (int j = 0; j < 8; j++)
            #pragma unroll
            for (int q = 0; q < 4; q++) acc[i][j][q] = 0.f;

    int nIter = (K + BK - 1) >> 4;

    // preload chunk 0
    {
        int k0 = 0;
        #pragma unroll
        for (int p = 0; p < 2; ++p) {
            int f = p * 256 + tid;
            int r = f >> 2, c4 = f & 3;
            int gm = m0 + r;
            float v[4] = {0.f, 0.f, 0.f, 0.f};
            if (gm < M) {
                if (a_id == 2) {
                    if (k0 + 16 <= K) {
                        float4 t = *(const float4*)&Af[(size_t)gm * lda + k0 + c4 * 4];
                        v[0] = t.x; v[1] = t.y; v[2] = t.z; v[3] = t.w;
                    } else {
                        #pragma unroll
                        for (int e = 0; e < 4; ++e) {
                            int gk = k0 + c4 * 4 + e;
                            if (gk < K) v[e] = Af[(size_t)gm * lda + gk];
                        }
                    }
                } else {
                    if (k0 + 16 <= K) {
                        uint2 t = *(const uint2*)&Ah[(size_t)gm * lda + k0 + c4 * 4];
                        __half2 h0 = *(__half2*)&t.x, h1 = *(__half2*)&t.y;
                        float2 f0 = __half22float2(h0), f1 = __half22float2(h1);
                        v[0] = f0.x; v[1] = f0.y; v[2] = f1.x; v[3] = f1.y;
                    } else {
                        #pragma unroll
                        for (int e = 0; e < 4; ++e) {
                            int gk = k0 + c4 * 4 + e;
                            if (gk < K) v[e] = __half2float(Ah[(size_t)gm * lda + gk]);
                        }
                    }
                }
            }
            As2[0][r][2 * c4]     = __floats2half2_rn(v[0], v[1]);
            As2[0][r][2 * c4 + 1] = __floats2half2_rn(v[2], v[3]);
        }
        #pragma unroll
        for (int p = 0; p < 4; ++p) {
            int e = p * 256 + tid;
            int r = e >> 7, c = e & 127;
            int gk = k0 + 2 * r, gn = n0 + c;
            float v0 = (gk < K && gn < Nn) ? B[(size_t)gk * ldb + gn] : 0.f;
            float v1 = (gk + 1 < K && gn < Nn) ? B[(size_t)(gk + 1) * ldb + gn] : 0.f;
            Bs2[0][r][c] = __floats2half2_rn(v0, v1);
        }
    }
    __syncthreads();

    int buf = 0;
    for (int it = 0; it < nIter; ++it) {
        bool hasNext = (it + 1) < nIter;
        int k1 = (it + 1) << 4;
        float ra[2][4];
        float rb[4][2];
        if (hasNext) {
            #pragma unroll
            for (int p = 0; p < 2; ++p) {
                int f = p * 256 + tid;
                int r = f >> 2, c4 = f & 3;
                int gm = m0 + r;
                ra[p][0] = ra[p][1] = ra[p][2] = ra[p][3] = 0.f;
                if (gm < M) {
                    if (a_id == 2) {
                        if (k1 + 16 <= K) {
                            float4 t = *(const float4*)&Af[(size_t)gm * lda + k1 + c4 * 4];
                            ra[p][0] = t.x; ra[p][1] = t.y; ra[p][2] = t.z; ra[p][3] = t.w;
                        } else {
                            #pragma unroll
                            for (int e = 0; e < 4; ++e) {
                                int gk = k1 + c4 * 4 + e;
                                if (gk < K) ra[p][e] = Af[(size_t)gm * lda + gk];
                            }
                        }
                    } else {
                        if (k1 + 16 <= K) {
                            uint2 t = *(const uint2*)&Ah[(size_t)gm * lda + k1 + c4 * 4];
                            __half2 h0 = *(__half2*)&t.x, h1 = *(__half2*)&t.y;
                            float2 f0 = __half22float2(h0), f1 = __half22float2(h1);
                            ra[p][0] = f0.x; ra[p][1] = f0.y; ra[p][2] = f1.x; ra[p][3] = f1.y;
                        } else {
                            #pragma unroll
                            for (int e = 0; e < 4; ++e) {
                                int gk = k1 + c4 * 4 + e;
                                if (gk < K) ra[p][e] = __half2float(Ah[(size_t)gm * lda + gk]);
                            }
                        }
                    }
                }
            }
            #pragma unroll
            for (int p = 0; p < 4; ++p) {
                int e = p * 256 + tid;
                int r = e >> 7, c = e & 127;
                int gk = k1 + 2 * r, gn = n0 + c;
                rb[p][0] = (gk < K && gn < Nn) ? B[(size_t)gk * ldb + gn] : 0.f;
                rb[p][1] = (gk + 1 < K && gn < Nn) ? B[(size_t)(gk + 1) * ldb + gn] : 0.f;
            }
        }

        {
            uint32_t af[2][4];
            #pragma unroll
            for (int i = 0; i < 2; ++i) {
                int rA = wr * 32 + i * 16;
                af[i][0] = *(const uint32_t*)&As2[buf][rA + g    ][tig    ];
                af[i][1] = *(const uint32_t*)&As2[buf][rA + g + 8][tig    ];
                af[i][2] = *(const uint32_t*)&As2[buf][rA + g    ][tig + 4];
                af[i][3] = *(const uint32_t*)&As2[buf][rA + g + 8][tig + 4];
            }
            uint32_t bf[8][2];
            #pragma unroll
            for (int j = 0; j < 8; ++j) {
                int cB = wc * 64 + j * 8 + g;
                bf[j][0] = *(const uint32_t*)&Bs2[buf][tig    ][cB];
                bf[j][1] = *(const uint32_t*)&Bs2[buf][tig + 4][cB];
            }
            #pragma unroll
            for (int i = 0; i < 2; ++i)
                #pragma unroll
                for (int j = 0; j < 8; ++j) {
                    asm volatile(
                        "mma.sync.aligned.m16n8k16.row.col.f32.f16.f16.f32 "
                        "{%0,%1,%2,%3}, {%4,%5,%6,%7}, {%8,%9}, {%0,%1,%2,%3};"
                        : "+f"(acc[i][j][0]), "+f"(acc[i][j][1]),
                          "+f"(acc[i][j][2]), "+f"(acc[i][j][3])
                        : "r"(af[i][0]), "r"(af[i][1]), "r"(af[i][2]), "r"(af[i][3]),
                          "r"(bf[j][0]), "r"(bf[j][1]));
                }
        }

        if (hasNext) {
            int nb = buf ^ 1;
            #pragma unroll
            for (int p = 0; p < 2; ++p) {
                int f = p * 256 + tid;
                int r = f >> 2, c4 = f & 3;
                As2[nb][r][2 * c4]     = __floats2half2_rn(ra[p][0], ra[p][1]);
                As2[nb][r][2 * c4 + 1] = __floats2half2_rn(ra[p][2], ra[p][3]);
            }
            #pragma unroll
            for (int p = 0; p < 4; ++p) {
                int e = p * 256 + tid;
                int r = e >> 7, c = e & 127;
                Bs2[nb][r][c] = __floats2half2_rn(rb[p][0], rb[p][1]);
            }
        }
        __syncthreads();
        buf ^= 1;
    }

    #pragma unroll
    for (int i = 0; i < 2; ++i) {
        int r0 = m0 + wr * 32 + i * 16 + g;
        int r1 = r0 + 8;
        #pragma unroll
        for (int j = 0; j < 8; ++j) {
            int nn = n0 + wc * 64 + j * 8 + 2 * tig;
            if (nn < Nn) {
                float b0 = sbias[wc * 64 + j * 8 + 2 * tig];
                float b1 = sbias[wc * 64 + j * 8 + 2 * tig + 1];
                if (r0 < M)
                    C2[(size_t)r0 * ldc2 + (nn >> 1)] =
                        __floats2half2_rn(acc[i][j][0] + b0, acc[i][j][1] + b1);
                if (r1 < M)
                    C2[(size_t)r1 * ldc2 + (nn >> 1)] =
                        __floats2half2_rn(acc[i][j][2] + b0, acc[i][j][3] + b1);
            }
        }
    }
}

// ---------------- SpMM1: 2 warps per row (feature split) + tanh, half out ---

__global__ __launch_bounds__(256) void spmm1_tanh_h_kernel(int n)
{
    const uint4* Hh = (const uint4*)g_H;       // 8 halves per uint4, pitch 64
    uint4* Out4 = (uint4*)g_A;                 // pitch 64 uint4 (512 halves)

    int gw = (blockIdx.x * blockDim.x + threadIdx.x) >> 5;
    int row = gw >> 1, half = gw & 1;
    if (row >= n) return;
    int lane = threadIdx.x & 31;
    int idx = half * 32 + lane;
    bool valid = idx < 63;                     // 63 uint4 cover 504 >= 500 halves

    float2 acc[4];
    #pragma unroll
    for (int p = 0; p < 4; ++p) acc[p] = make_float2(0.f, 0.f);

    int s = g_rowptr[row], e = g_rowptr[row + 1];
    for (int j = s; j < e; ++j) {
        int   c  = __ldg(&g_colidx[j]);
        float wj = __ldg(&g_wnorm[j]);
        if (valid) {
            uint4 v = Hh[(size_t)c * 64 + idx];
            #pragma unroll
            for (int p = 0; p < 4; ++p) {
                float2 f = __half22float2(*(const __half2*)((&v.x) + p));
                acc[p].x += wj * f.x;
                acc[p].y += wj * f.y;
            }
        }
    }
    if (valid) {
        __half2 h0 = __floats2half2_rn(tanhf(acc[0].x), tanhf(acc[0].y));
        __half2 h1 = __floats2half2_rn(tanhf(acc[1].x), tanhf(acc[1].y));
        __half2 h2 = __floats2half2_rn(tanhf(acc[2].x), tanhf(acc[2].y));
        __half2 h3 = __floats2half2_rn(tanhf(acc[3].x), tanhf(acc[3].y));
        uint4 o;
        o.x = *(uint32_t*)&h0; o.y = *(uint32_t*)&h1;
        o.z = *(uint32_t*)&h2; o.w = *(uint32_t*)&h3;
        Out4[(size_t)row * 64 + idx] = o;
    }
}

// ---------------- fused: SpMM2 + tanh + gemm3 -> h3 (half, pitch 16) --------

__global__ __launch_bounds__(256) void spmm2_gemm3_kernel(
    const float* __restrict__ W3, const float* __restrict__ b3, int n)
{
    __shared__ float st[8][104];           // 8 rows x 100 tanh'd features
    __shared__ float W3s[H2D * NCLS];
    __shared__ float b3s[NCLS];

    int tid = threadIdx.x;
    for (int i = tid; i < H2D * NCLS; i += 256) W3s[i] = W3[i];
    if (tid < NCLS) b3s[tid] = b3[tid];

    int w = tid >> 5, lane = tid & 31;
    int row = blockIdx.x * 8 + w;
    const __half2* Hh = (const __half2*)g_H;   // pitch 64 half2 (128 halves)

    if (row < n) {
        float2 acc0 = make_float2(0.f, 0.f);
        float2 acc1 = make_float2(0.f, 0.f);
        int s = g_rowptr[row], e = g_rowptr[row + 1];
        for (int j = s; j < e; ++j) {
            int   c  = __ldg(&g_colidx[j]);
            float wj = __ldg(&g_wnorm[j]);
            const __half2* base = Hh + (size_t)c * 64;
            {
                float2 f = __half22float2(base[lane]);
                acc0.x += wj * f.x; acc0.y += wj * f.y;
            }
            if (lane < 18) {
                float2 f = __half22float2(base[lane + 32]);
                acc1.x += wj * f.x; acc1.y += wj * f.y;
            }
        }
        *(float2*)&st[w][2 * lane] = make_float2(tanhf(acc0.x), tanhf(acc0.y));
        if (lane < 18)
            *(float2*)&st[w][64 + 2 * lane] = make_float2(tanhf(acc1.x), tanhf(acc1.y));
    }
    __syncthreads();

    // gemm3: 8 rows x 16 cols, K=100
    if (tid < 128) {
        int r = tid >> 4, c = tid & 15;
        int grow = blockIdx.x * 8 + r;
        if (grow < n) {
            float a = b3s[c];
            #pragma unroll 4
            for (int k = 0; k < H2D; ++k) a += st[r][k] * W3s[k * NCLS + c];
            ((__half*)g_A)[(size_t)grow * NCLS + c] = __float2half(a);
        }
    }
}

// ---------------- spmm3 (half gather) + tanh + softmax -> out ---------------

__global__ __launch_bounds__(256) void spmm3_softmax_kernel(float* __restrict__ out, int n)
{
    int row = blockIdx.x * blockDim.x + threadIdx.x;
    if (row >= n) return;
    const uint4* Hh = (const uint4*)g_A;       // 2 uint4 per row (16 halves)

    float acc[NCLS];
    #pragma unroll
    for (int j = 0; j < NCLS; j++) acc[j] = 0.f;

    int s = g_rowptr[row], e = g_rowptr[row + 1];
    for (int j = s; j < e; ++j) {
        int   c  = __ldg(&g_colidx[j]);
        float wj = __ldg(&g_wnorm[j]);
        uint4 v0 = Hh[(size_t)c * 2];
        uint4 v1 = Hh[(size_t)c * 2 + 1];
        #pragma unroll
        for (int q = 0; q < 4; ++q) {
            float2 f = __half22float2(*(const __half2*)((&v0.x) + q));
            acc[2 * q] += wj * f.x; acc[2 * q + 1] += wj * f.y;
        }
        #pragma unroll
        for (int q = 0; q < 4; ++q) {
            float2 f = __half22float2(*(const __half2*)((&v1.x) + q));
            acc[8 + 2 * q] += wj * f.x; acc[8 + 2 * q + 1] += wj * f.y;
        }
    }
    float mx = -1e30f;
    #pragma unroll
    for (int j = 0; j < NCLS; j++) { acc[j] = tanhf(acc[j]); mx = fmaxf(mx, acc[j]); }
    float sum = 0.f;
    #pragma unroll
    for (int j = 0; j < NCLS; j++) { acc[j] = expf(acc[j] - mx); sum += acc[j]; }
    float inv = 1.f / sum;
    float* o = out + (size_t)row * NCLS;
    #pragma unroll
    for (int j = 0; j < NCLS; j++) o[j] = acc[j] * inv;
}

// ---------------- launch ----------------

extern "C" void kernel_launch(void* const* d_in, const int* in_sizes, int n_in,
                              void* d_out, int out_size)
{
    const float* x  = (const float*)d_in[0];
    const void*  ei = d_in[1];
    const float* W1 = (const float*)d_in[2];
    const float* b1 = (const float*)d_in[3];
    const float* W2 = (const float*)d_in[4];
    const float* b2 = (const float*)d_in[5];
    const float* W3 = (const float*)d_in[6];
    const float* b3 = (const float*)d_in[7];
    float* out = (float*)d_out;

    int n = in_sizes[0] / F_IN;   // 50000
    int E = in_sizes[1] / 2;      // 800000

    // fork a side stream: CSR build runs concurrently with GEMM1
    cudaStream_t s2;
    cudaStreamCreateWithFlags(&s2, cudaStreamNonBlocking);
    cudaEvent_t evFork, evJoin;
    cudaEventCreateWithFlags(&evFork, cudaEventDisableTiming);
    cudaEventCreateWithFlags(&evJoin, cudaEventDisableTiming);

    cudaEventRecord(evFork, 0);
    cudaStreamWaitEvent(s2, evFork, 0);

    // --- CSR build (stream s2) ---
    detect_init_kernel<<<1 + (n + 255) / 256, 256, 0, s2>>>((const long long*)ei, n);
    hist_kernel<<<(E + 255) / 256, 256, 0, s2>>>(ei, E);
    scan_p1_kernel<<<NB_SCAN, 256, 0, s2>>>(n);
    scan_p2_kernel<<<1, 256, 0, s2>>>();
    scan_p3_kernel<<<NB_SCAN, 256, 0, s2>>>(n);
    fill_kernel<<<(E + n + 255) / 256, 256, 0, s2>>>(ei, E, n);
    cudaEventRecord(evJoin, s2);

    // --- layer 1 GEMM (main stream, concurrent with CSR) ---
    {
        dim3 g((H1D + BN - 1) / BN, (n + BM - 1) / BM);
        gemm_mma_kernel<<<g, 256>>>(x, 2, F_IN, W1, H1D, b1, 256, n, H1D, F_IN);
    }

    // join: SpMM1 needs both CSR and GEMM1
    cudaStreamWaitEvent(0, evJoin, 0);
    spmm1_tanh_h_kernel<<<(n * 64 + 255) / 256, 256>>>(n);   // 2 warps / row

    // --- layer 2 GEMM: [N,500(half)]x[500,100] -> g_H half (pitch 64 half2)
    {
        dim3 g((H2D + BN - 1) / BN, (n + BM - 1) / BM);
        gemm_mma_kernel<<<g, 256>>>(nullptr, 1, 512, W2, H2D, b2, 64, n, H2D, H1D);
    }

    // --- fused SpMM2 + tanh + gemm3 -> g_A half (pitch 16)
    spmm2_gemm3_kernel<<<(n + 7) / 8, 256>>>(W3, b3, n);

    // --- spmm3 + tanh + softmax -> out
    spmm3_softmax_kernel<<<(n + 255) / 256, 256>>>(out, n);

    cudaEventDestroy(evFork);
    cudaEventDestroy(evJoin);
    cudaStreamDestroy(s2);
}